// round 1
// baseline (speedup 1.0000x reference)
#include <cuda_runtime.h>

// ---------------- problem constants ----------------
constexpr int B    = 4;
constexpr int SEQ  = 4096;
constexpr int DIM  = 512;
constexpr int H    = 8;
constexpr int DH   = 64;     // DIM / H
constexpr int LM   = 256;    // landmarks
constexpr int LSZ  = 16;     // SEQ / LM
constexpr int BH   = B * H;  // 32
constexpr int CK   = 33;     // conv kernel
constexpr int TOK  = B * SEQ;        // 16384
constexpr int QKVW = 3 * DIM;        // 1536

// ---------------- scratch (static device memory; no allocations) ----------------
__device__ float g_xn  [TOK * DIM];
__device__ float g_qkv [(long)TOK * QKVW];
__device__ float g_ql  [BH * LM * DH];
__device__ float g_kl  [BH * LM * DH];
__device__ float g_sim1[(long)BH * SEQ * LM];   // -> a1 (softmax in place)
__device__ float g_sim3[(long)BH * LM * SEQ];   // -> a3 (softmax in place)
__device__ float g_a2  [BH * LM * LM];
__device__ float g_z   [BH * LM * LM];
__device__ float g_z2  [BH * LM * LM];
__device__ float g_xz  [BH * LM * LM];
__device__ float g_t   [BH * LM * LM];
__device__ float g_w   [BH * LM * LM];
__device__ float g_a3v [BH * LM * DH];
__device__ float g_tmp [(long)BH * SEQ * LM];
__device__ float g_res [(long)BH * SEQ * DH];
__device__ float g_outh[(long)BH * SEQ * DH];
__device__ float g_ctx [TOK * DIM];
__device__ int   g_rowmax_i;
__device__ int   g_colmax_i;

// ---------------- batched SGEMM ----------------
// C[z] = alpha * A[z] @ op(B[z]) (+ bias[col]) (+ resid[z])
// Every operand addressed as base + zb*s1 + zh*s2, with z = zb*H + zh.
// Requires Mn%BM==0, Nn%BN==0, Kn%BK==0 (guaranteed by our shapes).
template<int BM, int BN, int BK, int TM, int TN, bool TB>
__global__ __launch_bounds__((BM/TM)*(BN/TN))
void gemm_k(const float* __restrict__ A, const float* __restrict__ Bm, float* __restrict__ C,
            int Mn, int Nn, int Kn, int lda, int ldb, int ldc,
            long sA1, long sA2, long sB1, long sB2, long sC1, long sC2,
            float alpha, const float* __restrict__ bias,
            const float* __restrict__ resid, long sR1, long sR2)
{
    const int zb = blockIdx.z / H;
    const int zh = blockIdx.z % H;
    A  += zb * sA1 + zh * sA2;
    Bm += zb * sB1 + zh * sB2;
    C  += zb * sC1 + zh * sC2;
    if (resid) resid += zb * sR1 + zh * sR2;

    __shared__ __align__(16) float As[BK][BM];
    __shared__ __align__(16) float Bs[BK][BN];

    const int tid = threadIdx.x;
    const int tx  = tid % (BN / TN);
    const int ty  = tid / (BN / TN);
    const int row0 = blockIdx.y * BM;
    const int col0 = blockIdx.x * BN;

    // loader mappings (exactly one float4 per thread per operand per tile)
    const int a_r  = tid / (BK / 4);
    const int a_c  = (tid % (BK / 4)) * 4;
    const int bn_r = tid / (BN / 4);
    const int bn_c = (tid % (BN / 4)) * 4;
    const int bt_r = tid / (BK / 4);
    const int bt_c = (tid % (BK / 4)) * 4;

    float acc[TM][TN];
#pragma unroll
    for (int i = 0; i < TM; i++)
#pragma unroll
        for (int j = 0; j < TN; j++) acc[i][j] = 0.f;

    for (int k0 = 0; k0 < Kn; k0 += BK) {
        float4 av = *reinterpret_cast<const float4*>(A + (long)(row0 + a_r) * lda + k0 + a_c);
        As[a_c + 0][a_r] = av.x; As[a_c + 1][a_r] = av.y;
        As[a_c + 2][a_r] = av.z; As[a_c + 3][a_r] = av.w;
        if (TB) {
            float4 bv = *reinterpret_cast<const float4*>(Bm + (long)(col0 + bt_r) * ldb + k0 + bt_c);
            Bs[bt_c + 0][bt_r] = bv.x; Bs[bt_c + 1][bt_r] = bv.y;
            Bs[bt_c + 2][bt_r] = bv.z; Bs[bt_c + 3][bt_r] = bv.w;
        } else {
            float4 bv = *reinterpret_cast<const float4*>(Bm + (long)(k0 + bn_r) * ldb + col0 + bn_c);
            *reinterpret_cast<float4*>(&Bs[bn_r][bn_c]) = bv;
        }
        __syncthreads();
#pragma unroll
        for (int kk = 0; kk < BK; kk++) {
            float af[TM], bf[TN];
#pragma unroll
            for (int f = 0; f < TM / 4; f++)
                *reinterpret_cast<float4*>(&af[f * 4]) =
                    *reinterpret_cast<const float4*>(&As[kk][ty * TM + f * 4]);
#pragma unroll
            for (int f = 0; f < TN / 4; f++)
                *reinterpret_cast<float4*>(&bf[f * 4]) =
                    *reinterpret_cast<const float4*>(&Bs[kk][tx * TN + f * 4]);
#pragma unroll
            for (int i = 0; i < TM; i++)
#pragma unroll
                for (int j = 0; j < TN; j++)
                    acc[i][j] = fmaf(af[i], bf[j], acc[i][j]);
        }
        __syncthreads();
    }

#pragma unroll
    for (int i = 0; i < TM; i++) {
        const int r = row0 + ty * TM + i;
#pragma unroll
        for (int j = 0; j < TN; j++) {
            const int c = col0 + tx * TN + j;
            float v = alpha * acc[i][j];
            if (bias)  v += bias[c];
            if (resid) v += resid[(long)r * ldc + c];
            C[(long)r * ldc + c] = v;
        }
    }
}

// ---------------- LayerNorm (one block per token) ----------------
__global__ void ln_kernel(const float* __restrict__ x, const float* __restrict__ gamma,
                          const float* __restrict__ beta, float* __restrict__ xn)
{
    const int t = blockIdx.x;
    const int tid = threadIdx.x;             // 256 threads, 2 elems each
    const float2 v = reinterpret_cast<const float2*>(x + (long)t * DIM)[tid];
    float s  = v.x + v.y;
    float ss = v.x * v.x + v.y * v.y;
#pragma unroll
    for (int o = 16; o; o >>= 1) {
        s  += __shfl_xor_sync(0xffffffffu, s,  o);
        ss += __shfl_xor_sync(0xffffffffu, ss, o);
    }
    __shared__ float sms[8], smss[8];
    __shared__ float mu_s, rs_s;
    if ((tid & 31) == 0) { sms[tid >> 5] = s; smss[tid >> 5] = ss; }
    __syncthreads();
    if (tid == 0) {
        float S = 0.f, SS = 0.f;
        for (int i = 0; i < 8; i++) { S += sms[i]; SS += smss[i]; }
        const float mu = S / DIM;
        mu_s = mu;
        rs_s = rsqrtf(SS / DIM - mu * mu + 1e-5f);
    }
    __syncthreads();
    const float mu = mu_s, rs = rs_s;
    const float2 g  = reinterpret_cast<const float2*>(gamma)[tid];
    const float2 be = reinterpret_cast<const float2*>(beta)[tid];
    float2 o;
    o.x = (v.x - mu) * rs * g.x + be.x;
    o.y = (v.y - mu) * rs * g.y + be.y;
    reinterpret_cast<float2*>(xn + (long)t * DIM)[tid] = o;
}

// ---------------- landmark means (q already scaled by dh^-0.5) ----------------
__global__ void landmark_kernel(const float* __restrict__ qkv,
                                float* __restrict__ ql, float* __restrict__ kl)
{
    const int idx = blockIdx.x * blockDim.x + threadIdx.x;   // BH*LM*DH
    if (idx >= BH * LM * DH) return;
    const int d  = idx % DH;
    const int j  = (idx / DH) % LM;
    const int bh = idx / (DH * LM);
    const int b = bh / H, h = bh % H;
    const float* base = qkv + ((long)(b * SEQ + j * LSZ)) * QKVW + h * DH + d;
    float sq = 0.f, sk = 0.f;
#pragma unroll
    for (int l = 0; l < LSZ; l++) {
        sq += base[(long)l * QKVW];
        sk += base[(long)l * QKVW + DIM];
    }
    ql[idx] = sq * (1.0f / LSZ) * 0.125f;   // includes q scale dh^-0.5
    kl[idx] = sk * (1.0f / LSZ);
}

// ---------------- softmax over rows of length 256 (1 warp / row) ----------------
__global__ void softmax256(float* __restrict__ data, int rows)
{
    const int warp = (blockIdx.x * blockDim.x + threadIdx.x) >> 5;
    const int lane = threadIdx.x & 31;
    if (warp >= rows) return;
    float* r = data + (long)warp * 256;
    float v[8];
    float mx = -1e30f;
#pragma unroll
    for (int j = 0; j < 8; j++) { v[j] = r[lane + j * 32]; mx = fmaxf(mx, v[j]); }
#pragma unroll
    for (int o = 16; o; o >>= 1) mx = fmaxf(mx, __shfl_xor_sync(0xffffffffu, mx, o));
    float s = 0.f;
#pragma unroll
    for (int j = 0; j < 8; j++) { v[j] = expf(v[j] - mx); s += v[j]; }
#pragma unroll
    for (int o = 16; o; o >>= 1) s += __shfl_xor_sync(0xffffffffu, s, o);
    const float inv = 1.0f / s;
#pragma unroll
    for (int j = 0; j < 8; j++) r[lane + j * 32] = v[j] * inv;
}

// ---------------- softmax over rows of length 4096 (1 block / row) ----------------
__global__ void softmax_wide(float* __restrict__ data)
{
    float* r = data + (long)blockIdx.x * SEQ;
    const int tid = threadIdx.x;            // 256 threads, 16 elems each
    float v[16];
    float mx = -1e30f;
#pragma unroll
    for (int j = 0; j < 16; j++) { v[j] = r[tid + j * 256]; mx = fmaxf(mx, v[j]); }
    __shared__ float sm[256];
    sm[tid] = mx; __syncthreads();
    for (int o = 128; o; o >>= 1) { if (tid < o) sm[tid] = fmaxf(sm[tid], sm[tid + o]); __syncthreads(); }
    mx = sm[0]; __syncthreads();
    float s = 0.f;
#pragma unroll
    for (int j = 0; j < 16; j++) { v[j] = expf(v[j] - mx); s += v[j]; }
    sm[tid] = s; __syncthreads();
    for (int o = 128; o; o >>= 1) { if (tid < o) sm[tid] += sm[tid + o]; __syncthreads(); }
    const float inv = 1.0f / sm[0];
#pragma unroll
    for (int j = 0; j < 16; j++) r[tid + j * 256] = v[j] * inv;
}

// ---------------- pinv helpers ----------------
__global__ void init_norms() { g_rowmax_i = 0; g_colmax_i = 0; }

__global__ void pinv_norms(const float* __restrict__ a2)
{
    const int bh = blockIdx.x, tid = threadIdx.x;   // 256 threads
    const float* X = a2 + (long)bh * LM * LM;
    float rs = 0.f, cs = 0.f;
    for (int j = 0; j < LM; j++) {
        rs += fabsf(X[(long)tid * LM + j]);
        cs += fabsf(X[(long)j * LM + tid]);
    }
    __shared__ float sm[256];
    sm[tid] = rs; __syncthreads();
    for (int o = 128; o; o >>= 1) { if (tid < o) sm[tid] = fmaxf(sm[tid], sm[tid + o]); __syncthreads(); }
    if (tid == 0) atomicMax(&g_rowmax_i, __float_as_int(sm[0]));
    __syncthreads();
    sm[tid] = cs; __syncthreads();
    for (int o = 128; o; o >>= 1) { if (tid < o) sm[tid] = fmaxf(sm[tid], sm[tid + o]); __syncthreads(); }
    if (tid == 0) atomicMax(&g_colmax_i, __float_as_int(sm[0]));
}

__global__ void pinv_z0(const float* __restrict__ a2, float* __restrict__ z)
{
    const long idx = (long)blockIdx.x * blockDim.x + threadIdx.x;
    if (idx >= (long)BH * LM * LM) return;
    const float inv = 1.0f / (__int_as_float(g_rowmax_i) * __int_as_float(g_colmax_i));
    const int j  = (int)(idx % LM);
    const int i  = (int)((idx / LM) % LM);
    const int bh = (int)(idx / ((long)LM * LM));
    z[idx] = a2[(long)bh * LM * LM + (long)j * LM + i] * inv;   // transpose * inv
}

__global__ void aI_minus(const float* __restrict__ in, float* __restrict__ out, float a)
{
    const long idx = (long)blockIdx.x * blockDim.x + threadIdx.x;
    if (idx >= (long)BH * LM * LM) return;
    const int j = (int)(idx % LM);
    const int i = (int)((idx / LM) % LM);
    out[idx] = (i == j ? a : 0.0f) - in[idx];
}

// ---------------- depthwise conv over sequence (kernel 33) ----------------
__global__ void conv_kernel(const float* __restrict__ qkv, const float* __restrict__ w,
                            float* __restrict__ res)
{
    const int bh = blockIdx.y;
    const int b = bh / H, h = bh % H;
    const int i0 = blockIdx.x * 64;
    __shared__ float sm[96][DH];
    __shared__ float wsh[CK];
    const int tid = threadIdx.x;
    if (tid < CK) wsh[tid] = w[h * CK + tid];
    const float* vbase = qkv + 2 * DIM + h * DH + (long)b * SEQ * QKVW;
    for (int e = tid; e < 96 * DH; e += 256) {
        const int r = e / DH, d = e % DH;
        const int gi = i0 + r - 16;
        sm[r][d] = (gi >= 0 && gi < SEQ) ? vbase[(long)gi * QKVW + d] : 0.0f;
    }
    __syncthreads();
    float* rbase = res + (long)bh * SEQ * DH + (long)i0 * DH;
    for (int e = tid; e < 64 * DH; e += 256) {
        const int il = e / DH, d = e % DH;
        float s = 0.f;
#pragma unroll
        for (int t = 0; t < CK; t++) s = fmaf(sm[il + t][d], wsh[t], s);
        rbase[e] = s;
    }
}

// ---------------- reorder (b,h,n,dh) -> (b,n,h*dh) ----------------
__global__ void reorder_kernel(const float* __restrict__ outh, float* __restrict__ ctx)
{
    const long idx = (long)blockIdx.x * blockDim.x + threadIdx.x;
    if (idx >= (long)BH * SEQ * DH) return;
    const int d  = (int)(idx % DH);
    const int i  = (int)((idx / DH) % SEQ);
    const int bh = (int)(idx / ((long)DH * SEQ));
    const int b = bh / H, h = bh % H;
    ctx[((long)(b * SEQ + i)) * DIM + h * DH + d] = outh[idx];
}

// ---------------- host orchestration ----------------
extern "C" void kernel_launch(void* const* d_in, const int* in_sizes, int n_in,
                              void* d_out, int out_size)
{
    const float* x     = (const float*)d_in[0];
    const float* gamma = (const float*)d_in[1];
    const float* beta  = (const float*)d_in[2];
    const float* Wqkv  = (const float*)d_in[3];
    const float* Wout  = (const float*)d_in[4];
    const float* bout  = (const float*)d_in[5];
    const float* convw = (const float*)d_in[6];
    float* out = (float*)d_out;

    float *p_xn, *p_qkv, *p_ql, *p_kl, *p_sim1, *p_sim3, *p_a2, *p_z, *p_z2,
          *p_xz, *p_t, *p_w, *p_a3v, *p_tmp, *p_res, *p_outh, *p_ctx;
    cudaGetSymbolAddress((void**)&p_xn,   g_xn);
    cudaGetSymbolAddress((void**)&p_qkv,  g_qkv);
    cudaGetSymbolAddress((void**)&p_ql,   g_ql);
    cudaGetSymbolAddress((void**)&p_kl,   g_kl);
    cudaGetSymbolAddress((void**)&p_sim1, g_sim1);
    cudaGetSymbolAddress((void**)&p_sim3, g_sim3);
    cudaGetSymbolAddress((void**)&p_a2,   g_a2);
    cudaGetSymbolAddress((void**)&p_z,    g_z);
    cudaGetSymbolAddress((void**)&p_z2,   g_z2);
    cudaGetSymbolAddress((void**)&p_xz,   g_xz);
    cudaGetSymbolAddress((void**)&p_t,    g_t);
    cudaGetSymbolAddress((void**)&p_w,    g_w);
    cudaGetSymbolAddress((void**)&p_a3v,  g_a3v);
    cudaGetSymbolAddress((void**)&p_tmp,  g_tmp);
    cudaGetSymbolAddress((void**)&p_res,  g_res);
    cudaGetSymbolAddress((void**)&p_outh, g_outh);
    cudaGetSymbolAddress((void**)&p_ctx,  g_ctx);

    const long sQKVb = (long)SEQ * QKVW;        // per-b stride in qkv view
    const long sLD_b = (long)H * LM * DH, sLD_h = (long)LM * DH;     // [bh][LM][DH]
    const long sS1_b = (long)H * SEQ * LM, sS1_h = (long)SEQ * LM;   // [bh][SEQ][LM]
    const long sS3_b = (long)H * LM * SEQ, sS3_h = (long)LM * SEQ;   // [bh][LM][SEQ]
    const long sMM_b = (long)H * LM * LM,  sMM_h = (long)LM * LM;    // [bh][LM][LM]
    const long sOH_b = (long)H * SEQ * DH, sOH_h = (long)SEQ * DH;   // [bh][SEQ][DH]

    // 1) LayerNorm
    ln_kernel<<<TOK, 256>>>(x, gamma, beta, p_xn);

    // 2) QKV projection: (16384x512) @ (512x1536)
    gemm_k<128,128,8,8,8,false><<<dim3(QKVW/128, TOK/128, 1), 256>>>(
        p_xn, Wqkv, p_qkv, TOK, QKVW, DIM, DIM, QKVW, QKVW,
        0,0, 0,0, 0,0, 1.0f, nullptr, nullptr, 0,0);

    // 3) landmarks
    landmark_kernel<<<(BH*LM*DH)/256, 256>>>(p_qkv, p_ql, p_kl);

    // 4) sim1 = scale * q @ k_l^T   (batched, q is a view into qkv)
    gemm_k<128,128,8,8,8,true><<<dim3(LM/128, SEQ/128, BH), 256>>>(
        p_qkv, p_kl, p_sim1, SEQ, LM, DH, QKVW, DH, LM,
        sQKVb, DH, sLD_b, sLD_h, sS1_b, sS1_h, 0.125f, nullptr, nullptr, 0,0);

    // 5) sim2 = q_l @ k_l^T
    gemm_k<128,128,8,8,8,true><<<dim3(LM/128, LM/128, BH), 256>>>(
        p_ql, p_kl, p_a2, LM, LM, DH, DH, DH, LM,
        sLD_b, sLD_h, sLD_b, sLD_h, sMM_b, sMM_h, 1.0f, nullptr, nullptr, 0,0);

    // 6) sim3 = q_l @ k^T   (k is a view into qkv at +DIM)
    gemm_k<128,128,8,8,8,true><<<dim3(SEQ/128, LM/128, BH), 256>>>(
        p_ql, p_qkv + DIM, p_sim3, LM, SEQ, DH, DH, QKVW, SEQ,
        sLD_b, sLD_h, sQKVb, DH, sS3_b, sS3_h, 1.0f, nullptr, nullptr, 0,0);

    // 7) softmaxes
    softmax256<<<(BH*SEQ)/8, 256>>>(p_sim1, BH*SEQ);   // a1
    softmax256<<<(BH*LM)/8, 256>>>(p_a2, BH*LM);       // a2
    softmax_wide<<<BH*LM, 256>>>(p_sim3);              // a3

    // 8) pinv(a2) via Newton-Schulz
    init_norms<<<1,1>>>();
    pinv_norms<<<BH, 256>>>(p_a2);
    pinv_z0<<<(BH*LM*LM)/256, 256>>>(p_a2, p_z);
    for (int it = 0; it < 6; it++) {
        float* zin  = (it & 1) ? p_z2 : p_z;
        float* zout = (it & 1) ? p_z  : p_z2;
        // xz = a2 @ z
        gemm_k<128,128,8,8,8,false><<<dim3(2,2,BH), 256>>>(
            p_a2, zin, p_xz, LM, LM, LM, LM, LM, LM,
            sMM_b, sMM_h, sMM_b, sMM_h, sMM_b, sMM_h, 1.0f, nullptr, nullptr, 0,0);
        aI_minus<<<(BH*LM*LM)/256, 256>>>(p_xz, p_t, 7.0f);
        gemm_k<128,128,8,8,8,false><<<dim3(2,2,BH), 256>>>(
            p_xz, p_t, p_w, LM, LM, LM, LM, LM, LM,
            sMM_b, sMM_h, sMM_b, sMM_h, sMM_b, sMM_h, 1.0f, nullptr, nullptr, 0,0);
        aI_minus<<<(BH*LM*LM)/256, 256>>>(p_w, p_t, 15.0f);
        gemm_k<128,128,8,8,8,false><<<dim3(2,2,BH), 256>>>(
            p_xz, p_t, p_w, LM, LM, LM, LM, LM, LM,
            sMM_b, sMM_h, sMM_b, sMM_h, sMM_b, sMM_h, 1.0f, nullptr, nullptr, 0,0);
        aI_minus<<<(BH*LM*LM)/256, 256>>>(p_w, p_t, 13.0f);
        // z_out = 0.25 * z_in @ t
        gemm_k<128,128,8,8,8,false><<<dim3(2,2,BH), 256>>>(
            zin, p_t, zout, LM, LM, LM, LM, LM, LM,
            sMM_b, sMM_h, sMM_b, sMM_h, sMM_b, sMM_h, 0.25f, nullptr, nullptr, 0,0);
    }
    // final z in p_z (6 swaps)

    // 9) a3v = a3 @ v   (v is a view into qkv at +2*DIM)
    gemm_k<64,64,16,4,4,false><<<dim3(1, LM/64, BH), 256>>>(
        p_sim3, p_qkv + 2*DIM, p_a3v, LM, DH, SEQ, SEQ, QKVW, DH,
        sS3_b, sS3_h, sQKVb, DH, sLD_b, sLD_h, 1.0f, nullptr, nullptr, 0,0);

    // 10) tmp = a1 @ a2_inv
    gemm_k<128,128,8,8,8,false><<<dim3(LM/128, SEQ/128, BH), 256>>>(
        p_sim1, p_z, p_tmp, SEQ, LM, LM, LM, LM, LM,
        sS1_b, sS1_h, sMM_b, sMM_h, sS1_b, sS1_h, 1.0f, nullptr, nullptr, 0,0);

    // 11) depthwise conv residual over v
    conv_kernel<<<dim3(SEQ/64, BH), 256>>>(p_qkv, convw, p_res);

    // 12) outh = tmp @ a3v + conv_res
    gemm_k<64,64,16,4,4,false><<<dim3(1, SEQ/64, BH), 256>>>(
        p_tmp, p_a3v, p_outh, SEQ, DH, LM, LM, DH, DH,
        sS1_b, sS1_h, sLD_b, sLD_h, sOH_b, sOH_h, 1.0f, nullptr, p_res, sOH_b, sOH_h);

    // 13) reorder to (b, n, dim)
    reorder_kernel<<<(BH*SEQ*DH)/256, 256>>>(p_outh, p_ctx);

    // 14) final: out = ctx @ W_out + b_out + x
    gemm_k<128,128,8,8,8,false><<<dim3(DIM/128, TOK/128, 1), 256>>>(
        p_ctx, Wout, out, TOK, DIM, DIM, DIM, DIM, DIM,
        0,0, 0,0, 0,0, 1.0f, bout, x, 0,0);
}

// round 3
// speedup vs baseline: 1.2404x; 1.2404x over previous
#include <cuda_runtime.h>

// ---------------- problem constants ----------------
constexpr int B    = 4;
constexpr int SEQ  = 4096;
constexpr int DIM  = 512;
constexpr int H    = 8;
constexpr int DH   = 64;     // DIM / H
constexpr int LM   = 256;    // landmarks
constexpr int LSZ  = 16;     // SEQ / LM
constexpr int BH   = B * H;  // 32
constexpr int CK   = 33;     // conv kernel
constexpr int TOK  = B * SEQ;        // 16384
constexpr int QKVW = 3 * DIM;        // 1536

// ---------------- scratch (static device memory; no allocations) ----------------
__device__ float g_xn  [TOK * DIM];
__device__ float g_qkv [(long)TOK * QKVW];
__device__ float g_ql  [BH * LM * DH];
__device__ float g_kl  [BH * LM * DH];
__device__ float g_sim1[(long)BH * SEQ * LM];   // -> a1 (softmax in place)
__device__ float g_sim3[(long)BH * LM * SEQ];   // -> a3 (softmax in place)
__device__ float g_a2  [BH * LM * LM];
__device__ float g_z   [BH * LM * LM];
__device__ float g_z2  [BH * LM * LM];
__device__ float g_xz  [BH * LM * LM];
__device__ float g_t   [BH * LM * LM];
__device__ float g_w   [BH * LM * LM];
__device__ float g_a3v [BH * LM * DH];
__device__ float g_za3v[BH * LM * DH];
__device__ float g_res [(long)BH * SEQ * DH];
__device__ float g_outh[(long)BH * SEQ * DH];
__device__ float g_ctx [TOK * DIM];
__device__ int   g_rowmax_i;
__device__ int   g_colmax_i;

// ---------------- batched SGEMM (pipelined: register prefetch of next slab) ----
// C[z] = alpha * A[z] @ op(B[z]) (+ bias[col]) (+ resid[z])
// Every operand addressed as base + zb*s1 + zh*s2, with z = zb*H + zh.
// Requires Mn%BM==0, Nn%BN==0, Kn%BK==0 (guaranteed by our shapes).
template<int BM, int BN, int BK, int TM, int TN, bool TB>
__global__ __launch_bounds__((BM/TM)*(BN/TN), 2)
void gemm_k(const float* __restrict__ A, const float* __restrict__ Bm, float* __restrict__ C,
            int Mn, int Nn, int Kn, int lda, int ldb, int ldc,
            long sA1, long sA2, long sB1, long sB2, long sC1, long sC2,
            float alpha, const float* __restrict__ bias,
            const float* __restrict__ resid, long sR1, long sR2)
{
    constexpr int NT = (BM / TM) * (BN / TN);
    constexpr int LA = BM * BK / (4 * NT);   // float4 loads/thread for A slab
    constexpr int LB = BN * BK / (4 * NT);   // float4 loads/thread for B slab

    const int zb = blockIdx.z / H;
    const int zh = blockIdx.z % H;
    A  += zb * sA1 + zh * sA2;
    Bm += zb * sB1 + zh * sB2;
    C  += zb * sC1 + zh * sC2;
    if (resid) resid += zb * sR1 + zh * sR2;

    __shared__ __align__(16) float As[BK][BM];
    __shared__ __align__(16) float Bs[BK][BN];

    const int tid = threadIdx.x;
    const int tx  = tid % (BN / TN);
    const int ty  = tid / (BN / TN);
    const int row0 = blockIdx.y * BM;
    const int col0 = blockIdx.x * BN;

    // loader coordinates
    int rA[LA], cA[LA];
#pragma unroll
    for (int i = 0; i < LA; i++) {
        const int idx = tid + i * NT;
        rA[i] = idx / (BK / 4);
        cA[i] = (idx % (BK / 4)) * 4;
    }
    int rB[LB], cB[LB];
#pragma unroll
    for (int i = 0; i < LB; i++) {
        const int idx = tid + i * NT;
        if (TB) { rB[i] = idx / (BK / 4); cB[i] = (idx % (BK / 4)) * 4; }
        else    { rB[i] = idx / (BN / 4); cB[i] = (idx % (BN / 4)) * 4; }
    }

    float4 pa[LA], pb[LB];
    auto loadG = [&](int k0) {
#pragma unroll
        for (int i = 0; i < LA; i++)
            pa[i] = *reinterpret_cast<const float4*>(A + (long)(row0 + rA[i]) * lda + k0 + cA[i]);
#pragma unroll
        for (int i = 0; i < LB; i++) {
            if (TB) pb[i] = *reinterpret_cast<const float4*>(Bm + (long)(col0 + rB[i]) * ldb + k0 + cB[i]);
            else    pb[i] = *reinterpret_cast<const float4*>(Bm + (long)(k0 + rB[i]) * ldb + col0 + cB[i]);
        }
    };
    auto storeS = [&]() {
#pragma unroll
        for (int i = 0; i < LA; i++) {
            As[cA[i] + 0][rA[i]] = pa[i].x; As[cA[i] + 1][rA[i]] = pa[i].y;
            As[cA[i] + 2][rA[i]] = pa[i].z; As[cA[i] + 3][rA[i]] = pa[i].w;
        }
#pragma unroll
        for (int i = 0; i < LB; i++) {
            if (TB) {
                Bs[cB[i] + 0][rB[i]] = pb[i].x; Bs[cB[i] + 1][rB[i]] = pb[i].y;
                Bs[cB[i] + 2][rB[i]] = pb[i].z; Bs[cB[i] + 3][rB[i]] = pb[i].w;
            } else {
                *reinterpret_cast<float4*>(&Bs[rB[i]][cB[i]]) = pb[i];
            }
        }
    };

    float acc[TM][TN];
#pragma unroll
    for (int i = 0; i < TM; i++)
#pragma unroll
        for (int j = 0; j < TN; j++) acc[i][j] = 0.f;

    loadG(0);
    for (int k0 = 0; k0 < Kn; k0 += BK) {
        storeS();
        __syncthreads();
        if (k0 + BK < Kn) loadG(k0 + BK);   // overlap next-slab GMEM with compute
#pragma unroll
        for (int kk = 0; kk < BK; kk++) {
            float af[TM], bf[TN];
#pragma unroll
            for (int f = 0; f < TM / 4; f++)
                *reinterpret_cast<float4*>(&af[f * 4]) =
                    *reinterpret_cast<const float4*>(&As[kk][ty * TM + f * 4]);
#pragma unroll
            for (int f = 0; f < TN / 4; f++)
                *reinterpret_cast<float4*>(&bf[f * 4]) =
                    *reinterpret_cast<const float4*>(&Bs[kk][tx * TN + f * 4]);
#pragma unroll
            for (int i = 0; i < TM; i++)
#pragma unroll
                for (int j = 0; j < TN; j++)
                    acc[i][j] = fmaf(af[i], bf[j], acc[i][j]);
        }
        __syncthreads();
    }

#pragma unroll
    for (int i = 0; i < TM; i++) {
        const int r = row0 + ty * TM + i;
#pragma unroll
        for (int j = 0; j < TN; j++) {
            const int c = col0 + tx * TN + j;
            float v = alpha * acc[i][j];
            if (bias)  v += bias[c];
            if (resid) v += resid[(long)r * ldc + c];
            C[(long)r * ldc + c] = v;
        }
    }
}

// ---------------- LayerNorm (one block per token) ----------------
__global__ void ln_kernel(const float* __restrict__ x, const float* __restrict__ gamma,
                          const float* __restrict__ beta, float* __restrict__ xn)
{
    const int t = blockIdx.x;
    const int tid = threadIdx.x;             // 256 threads, 2 elems each
    const float2 v = reinterpret_cast<const float2*>(x + (long)t * DIM)[tid];
    float s  = v.x + v.y;
    float ss = v.x * v.x + v.y * v.y;
#pragma unroll
    for (int o = 16; o; o >>= 1) {
        s  += __shfl_xor_sync(0xffffffffu, s,  o);
        ss += __shfl_xor_sync(0xffffffffu, ss, o);
    }
    __shared__ float sms[8], smss[8];
    __shared__ float mu_s, rs_s;
    if ((tid & 31) == 0) { sms[tid >> 5] = s; smss[tid >> 5] = ss; }
    __syncthreads();
    if (tid == 0) {
        float S = 0.f, SS = 0.f;
        for (int i = 0; i < 8; i++) { S += sms[i]; SS += smss[i]; }
        const float mu = S / DIM;
        mu_s = mu;
        rs_s = rsqrtf(SS / DIM - mu * mu + 1e-5f);
    }
    __syncthreads();
    const float mu = mu_s, rs = rs_s;
    const float2 g  = reinterpret_cast<const float2*>(gamma)[tid];
    const float2 be = reinterpret_cast<const float2*>(beta)[tid];
    float2 o;
    o.x = (v.x - mu) * rs * g.x + be.x;
    o.y = (v.y - mu) * rs * g.y + be.y;
    reinterpret_cast<float2*>(xn + (long)t * DIM)[tid] = o;
}

// ---------------- landmark means (q already scaled by dh^-0.5) ----------------
__global__ void landmark_kernel(const float* __restrict__ qkv,
                                float* __restrict__ ql, float* __restrict__ kl)
{
    const int idx = blockIdx.x * blockDim.x + threadIdx.x;   // BH*LM*DH
    if (idx >= BH * LM * DH) return;
    const int d  = idx % DH;
    const int j  = (idx / DH) % LM;
    const int bh = idx / (DH * LM);
    const int b = bh / H, h = bh % H;
    const float* base = qkv + ((long)(b * SEQ + j * LSZ)) * QKVW + h * DH + d;
    float sq = 0.f, sk = 0.f;
#pragma unroll
    for (int l = 0; l < LSZ; l++) {
        sq += base[(long)l * QKVW];
        sk += base[(long)l * QKVW + DIM];
    }
    ql[idx] = sq * (1.0f / LSZ) * 0.125f;   // includes q scale dh^-0.5
    kl[idx] = sk * (1.0f / LSZ);
}

// ---------------- softmax over rows of length 256 (1 warp / row) ----------------
__global__ void softmax256(float* __restrict__ data, int rows)
{
    const int warp = (blockIdx.x * blockDim.x + threadIdx.x) >> 5;
    const int lane = threadIdx.x & 31;
    if (warp >= rows) return;
    float* r = data + (long)warp * 256;
    float v[8];
    float mx = -1e30f;
#pragma unroll
    for (int j = 0; j < 8; j++) { v[j] = r[lane + j * 32]; mx = fmaxf(mx, v[j]); }
#pragma unroll
    for (int o = 16; o; o >>= 1) mx = fmaxf(mx, __shfl_xor_sync(0xffffffffu, mx, o));
    float s = 0.f;
#pragma unroll
    for (int j = 0; j < 8; j++) { v[j] = expf(v[j] - mx); s += v[j]; }
#pragma unroll
    for (int o = 16; o; o >>= 1) s += __shfl_xor_sync(0xffffffffu, s, o);
    const float inv = 1.0f / s;
#pragma unroll
    for (int j = 0; j < 8; j++) r[lane + j * 32] = v[j] * inv;
}

// ---------------- softmax over rows of length 4096 (1 block / row) ----------------
__global__ void softmax_wide(float* __restrict__ data)
{
    float* r = data + (long)blockIdx.x * SEQ;
    const int tid = threadIdx.x;            // 256 threads, 16 elems each
    float v[16];
    float mx = -1e30f;
#pragma unroll
    for (int j = 0; j < 16; j++) { v[j] = r[tid + j * 256]; mx = fmaxf(mx, v[j]); }
    __shared__ float sm[256];
    sm[tid] = mx; __syncthreads();
    for (int o = 128; o; o >>= 1) { if (tid < o) sm[tid] = fmaxf(sm[tid], sm[tid + o]); __syncthreads(); }
    mx = sm[0]; __syncthreads();
    float s = 0.f;
#pragma unroll
    for (int j = 0; j < 16; j++) { v[j] = expf(v[j] - mx); s += v[j]; }
    sm[tid] = s; __syncthreads();
    for (int o = 128; o; o >>= 1) { if (tid < o) sm[tid] += sm[tid + o]; __syncthreads(); }
    const float inv = 1.0f / sm[0];
#pragma unroll
    for (int j = 0; j < 16; j++) r[tid + j * 256] = v[j] * inv;
}

// ---------------- pinv helpers ----------------
__global__ void init_norms() { g_rowmax_i = 0; g_colmax_i = 0; }

__global__ void pinv_norms(const float* __restrict__ a2)
{
    const int bh = blockIdx.x, tid = threadIdx.x;   // 256 threads
    const float* X = a2 + (long)bh * LM * LM;
    float rs = 0.f, cs = 0.f;
    for (int j = 0; j < LM; j++) {
        rs += fabsf(X[(long)tid * LM + j]);
        cs += fabsf(X[(long)j * LM + tid]);
    }
    __shared__ float sm[256];
    sm[tid] = rs; __syncthreads();
    for (int o = 128; o; o >>= 1) { if (tid < o) sm[tid] = fmaxf(sm[tid], sm[tid + o]); __syncthreads(); }
    if (tid == 0) atomicMax(&g_rowmax_i, __float_as_int(sm[0]));
    __syncthreads();
    sm[tid] = cs; __syncthreads();
    for (int o = 128; o; o >>= 1) { if (tid < o) sm[tid] = fmaxf(sm[tid], sm[tid + o]); __syncthreads(); }
    if (tid == 0) atomicMax(&g_colmax_i, __float_as_int(sm[0]));
}

__global__ void pinv_z0(const float* __restrict__ a2, float* __restrict__ z)
{
    const long idx = (long)blockIdx.x * blockDim.x + threadIdx.x;
    if (idx >= (long)BH * LM * LM) return;
    const float inv = 1.0f / (__int_as_float(g_rowmax_i) * __int_as_float(g_colmax_i));
    const int j  = (int)(idx % LM);
    const int i  = (int)((idx / LM) % LM);
    const int bh = (int)(idx / ((long)LM * LM));
    z[idx] = a2[(long)bh * LM * LM + (long)j * LM + i] * inv;   // transpose * inv
}

__global__ void aI_minus(const float* __restrict__ in, float* __restrict__ out, float a)
{
    const long idx = (long)blockIdx.x * blockDim.x + threadIdx.x;
    if (idx >= (long)BH * LM * LM) return;
    const int j = (int)(idx % LM);
    const int i = (int)((idx / LM) % LM);
    out[idx] = (i == j ? a : 0.0f) - in[idx];
}

// ---------------- depthwise conv over sequence (kernel 33) ----------------
__global__ void conv_kernel(const float* __restrict__ qkv, const float* __restrict__ w,
                            float* __restrict__ res)
{
    const int bh = blockIdx.y;
    const int b = bh / H, h = bh % H;
    const int i0 = blockIdx.x * 64;
    __shared__ float sm[96][DH];
    __shared__ float wsh[CK];
    const int tid = threadIdx.x;
    if (tid < CK) wsh[tid] = w[h * CK + tid];
    const float* vbase = qkv + 2 * DIM + h * DH + (long)b * SEQ * QKVW;
    for (int e = tid; e < 96 * DH; e += 256) {
        const int r = e / DH, d = e % DH;
        const int gi = i0 + r - 16;
        sm[r][d] = (gi >= 0 && gi < SEQ) ? vbase[(long)gi * QKVW + d] : 0.0f;
    }
    __syncthreads();
    float* rbase = res + (long)bh * SEQ * DH + (long)i0 * DH;
    for (int e = tid; e < 64 * DH; e += 256) {
        const int il = e / DH, d = e % DH;
        float s = 0.f;
#pragma unroll
        for (int t = 0; t < CK; t++) s = fmaf(sm[il + t][d], wsh[t], s);
        rbase[e] = s;
    }
}

// ---------------- reorder (b,h,n,dh) -> (b,n,h*dh) ----------------
__global__ void reorder_kernel(const float* __restrict__ outh, float* __restrict__ ctx)
{
    const long idx = (long)blockIdx.x * blockDim.x + threadIdx.x;
    if (idx >= (long)BH * SEQ * DH) return;
    const int d  = (int)(idx % DH);
    const int i  = (int)((idx / DH) % SEQ);
    const int bh = (int)(idx / ((long)DH * SEQ));
    const int b = bh / H, h = bh % H;
    ctx[((long)(b * SEQ + i)) * DIM + h * DH + d] = outh[idx];
}

// ---------------- host orchestration ----------------
extern "C" void kernel_launch(void* const* d_in, const int* in_sizes, int n_in,
                              void* d_out, int out_size)
{
    const float* x     = (const float*)d_in[0];
    const float* gamma = (const float*)d_in[1];
    const float* beta  = (const float*)d_in[2];
    const float* Wqkv  = (const float*)d_in[3];
    const float* Wout  = (const float*)d_in[4];
    const float* bout  = (const float*)d_in[5];
    const float* convw = (const float*)d_in[6];
    float* out = (float*)d_out;

    float *p_xn, *p_qkv, *p_ql, *p_kl, *p_sim1, *p_sim3, *p_a2, *p_z, *p_z2,
          *p_xz, *p_t, *p_w, *p_a3v, *p_za3v, *p_res, *p_outh, *p_ctx;
    cudaGetSymbolAddress((void**)&p_xn,   g_xn);
    cudaGetSymbolAddress((void**)&p_qkv,  g_qkv);
    cudaGetSymbolAddress((void**)&p_ql,   g_ql);
    cudaGetSymbolAddress((void**)&p_kl,   g_kl);
    cudaGetSymbolAddress((void**)&p_sim1, g_sim1);
    cudaGetSymbolAddress((void**)&p_sim3, g_sim3);
    cudaGetSymbolAddress((void**)&p_a2,   g_a2);
    cudaGetSymbolAddress((void**)&p_z,    g_z);
    cudaGetSymbolAddress((void**)&p_z2,   g_z2);
    cudaGetSymbolAddress((void**)&p_xz,   g_xz);
    cudaGetSymbolAddress((void**)&p_t,    g_t);
    cudaGetSymbolAddress((void**)&p_w,    g_w);
    cudaGetSymbolAddress((void**)&p_a3v,  g_a3v);
    cudaGetSymbolAddress((void**)&p_za3v, g_za3v);
    cudaGetSymbolAddress((void**)&p_res,  g_res);
    cudaGetSymbolAddress((void**)&p_outh, g_outh);
    cudaGetSymbolAddress((void**)&p_ctx,  g_ctx);

    const long sQKVb = (long)SEQ * QKVW;        // per-b stride in qkv view
    const long sLD_b = (long)H * LM * DH, sLD_h = (long)LM * DH;     // [bh][LM][DH]
    const long sS1_b = (long)H * SEQ * LM, sS1_h = (long)SEQ * LM;   // [bh][SEQ][LM]
    const long sS3_b = (long)H * LM * SEQ, sS3_h = (long)LM * SEQ;   // [bh][LM][SEQ]
    const long sMM_b = (long)H * LM * LM,  sMM_h = (long)LM * LM;    // [bh][LM][LM]
    const long sOH_b = (long)H * SEQ * DH, sOH_h = (long)SEQ * DH;   // [bh][SEQ][DH]

    // 1) LayerNorm
    ln_kernel<<<TOK, 256>>>(x, gamma, beta, p_xn);

    // 2) QKV projection: (16384x512) @ (512x1536)
    gemm_k<128,128,16,8,8,false><<<dim3(QKVW/128, TOK/128, 1), 256>>>(
        p_xn, Wqkv, p_qkv, TOK, QKVW, DIM, DIM, QKVW, QKVW,
        0,0, 0,0, 0,0, 1.0f, nullptr, nullptr, 0,0);

    // 3) landmarks
    landmark_kernel<<<(BH*LM*DH)/256, 256>>>(p_qkv, p_ql, p_kl);

    // 4) sim1 = scale * q @ k_l^T   (batched, q is a view into qkv)
    gemm_k<128,128,16,8,8,true><<<dim3(LM/128, SEQ/128, BH), 256>>>(
        p_qkv, p_kl, p_sim1, SEQ, LM, DH, QKVW, DH, LM,
        sQKVb, DH, sLD_b, sLD_h, sS1_b, sS1_h, 0.125f, nullptr, nullptr, 0,0);

    // 5) sim2 = q_l @ k_l^T
    gemm_k<128,128,16,8,8,true><<<dim3(LM/128, LM/128, BH), 256>>>(
        p_ql, p_kl, p_a2, LM, LM, DH, DH, DH, LM,
        sLD_b, sLD_h, sLD_b, sLD_h, sMM_b, sMM_h, 1.0f, nullptr, nullptr, 0,0);

    // 6) sim3 = q_l @ k^T   (k is a view into qkv at +DIM)
    gemm_k<128,128,16,8,8,true><<<dim3(SEQ/128, LM/128, BH), 256>>>(
        p_ql, p_qkv + DIM, p_sim3, LM, SEQ, DH, DH, QKVW, SEQ,
        sLD_b, sLD_h, sQKVb, DH, sS3_b, sS3_h, 1.0f, nullptr, nullptr, 0,0);

    // 7) softmaxes
    softmax256<<<(BH*SEQ)/8, 256>>>(p_sim1, BH*SEQ);   // a1
    softmax256<<<(BH*LM)/8, 256>>>(p_a2, BH*LM);       // a2
    softmax_wide<<<BH*LM, 256>>>(p_sim3);              // a3

    // 8) pinv(a2) via Newton-Schulz
    init_norms<<<1,1>>>();
    pinv_norms<<<BH, 256>>>(p_a2);
    pinv_z0<<<(BH*LM*LM)/256, 256>>>(p_a2, p_z);
    for (int it = 0; it < 6; it++) {
        float* zin  = (it & 1) ? p_z2 : p_z;
        float* zout = (it & 1) ? p_z  : p_z2;
        // xz = a2 @ z
        gemm_k<128,128,16,8,8,false><<<dim3(2,2,BH), 256>>>(
            p_a2, zin, p_xz, LM, LM, LM, LM, LM, LM,
            sMM_b, sMM_h, sMM_b, sMM_h, sMM_b, sMM_h, 1.0f, nullptr, nullptr, 0,0);
        aI_minus<<<(BH*LM*LM)/256, 256>>>(p_xz, p_t, 7.0f);
        gemm_k<128,128,16,8,8,false><<<dim3(2,2,BH), 256>>>(
            p_xz, p_t, p_w, LM, LM, LM, LM, LM, LM,
            sMM_b, sMM_h, sMM_b, sMM_h, sMM_b, sMM_h, 1.0f, nullptr, nullptr, 0,0);
        aI_minus<<<(BH*LM*LM)/256, 256>>>(p_w, p_t, 15.0f);
        gemm_k<128,128,16,8,8,false><<<dim3(2,2,BH), 256>>>(
            p_xz, p_t, p_w, LM, LM, LM, LM, LM, LM,
            sMM_b, sMM_h, sMM_b, sMM_h, sMM_b, sMM_h, 1.0f, nullptr, nullptr, 0,0);
        aI_minus<<<(BH*LM*LM)/256, 256>>>(p_w, p_t, 13.0f);
        // z_out = 0.25 * z_in @ t
        gemm_k<128,128,16,8,8,false><<<dim3(2,2,BH), 256>>>(
            zin, p_t, zout, LM, LM, LM, LM, LM, LM,
            sMM_b, sMM_h, sMM_b, sMM_h, sMM_b, sMM_h, 0.25f, nullptr, nullptr, 0,0);
    }
    // final z in p_z (6 swaps)

    // 9) a3v = a3 @ v   (v is a view into qkv at +2*DIM)
    gemm_k<64,64,16,4,4,false><<<dim3(1, LM/64, BH), 256>>>(
        p_sim3, p_qkv + 2*DIM, p_a3v, LM, DH, SEQ, SEQ, QKVW, DH,
        sS3_b, sS3_h, sQKVb, DH, sLD_b, sLD_h, 1.0f, nullptr, nullptr, 0,0);

    // 10) za3v = z @ a3v   (reassociated: (a1@z)@(a3@v) == a1@(z@(a3@v)))
    gemm_k<64,64,16,4,4,false><<<dim3(1, LM/64, BH), 256>>>(
        p_z, p_a3v, p_za3v, LM, DH, LM, LM, DH, DH,
        sMM_b, sMM_h, sLD_b, sLD_h, sLD_b, sLD_h, 1.0f, nullptr, nullptr, 0,0);

    // 11) depthwise conv residual over v
    conv_kernel<<<dim3(SEQ/64, BH), 256>>>(p_qkv, convw, p_res);

    // 12) outh = a1 @ za3v + conv_res
    gemm_k<64,64,16,4,4,false><<<dim3(1, SEQ/64, BH), 256>>>(
        p_sim1, p_za3v, p_outh, SEQ, DH, LM, LM, DH, DH,
        sS1_b, sS1_h, sLD_b, sLD_h, sOH_b, sOH_h, 1.0f, nullptr, p_res, sOH_b, sOH_h);

    // 13) reorder to (b, n, dim)
    reorder_kernel<<<(BH*SEQ*DH)/256, 256>>>(p_outh, p_ctx);

    // 14) final: out = ctx @ W_out + b_out + x
    gemm_k<128,128,16,8,8,false><<<dim3(DIM/128, TOK/128, 1), 256>>>(
        p_ctx, Wout, out, TOK, DIM, DIM, DIM, DIM, DIM,
        0,0, 0,0, 0,0, 1.0f, bout, x, 0,0);
}

// round 5
// speedup vs baseline: 2.8642x; 2.3091x over previous
#include <cuda_runtime.h>
#include <cstdint>

// ---------------- problem constants ----------------
constexpr int B    = 4;
constexpr int SEQ  = 4096;
constexpr int DIM  = 512;
constexpr int H    = 8;
constexpr int DH   = 64;     // DIM / H
constexpr int LM   = 256;    // landmarks
constexpr int LSZ  = 16;     // SEQ / LM
constexpr int BH   = B * H;  // 32
constexpr int CK   = 33;     // conv kernel
constexpr int TOK  = B * SEQ;        // 16384
constexpr int QKVW = 3 * DIM;        // 1536

// ---------------- scratch (static device memory; no allocations) ----------------
__device__ float g_xn  [TOK * DIM];
__device__ float g_qkv [(long)TOK * QKVW];
__device__ float g_ql  [BH * LM * DH];
__device__ float g_kl  [BH * LM * DH];
__device__ float g_sim1[(long)BH * SEQ * LM];   // -> a1 (softmax in place)
__device__ float g_sim3[(long)BH * LM * SEQ];   // -> a3 (softmax in place)
__device__ float g_a2  [BH * LM * LM];
__device__ float g_z   [BH * LM * LM];
__device__ float g_z2  [BH * LM * LM];
__device__ float g_xz  [BH * LM * LM];
__device__ float g_t   [BH * LM * LM];
__device__ float g_w   [BH * LM * LM];
__device__ float g_a3v [BH * LM * DH];
__device__ float g_za3v[BH * LM * DH];
__device__ float g_res [(long)BH * SEQ * DH];
__device__ float g_outh[(long)BH * SEQ * DH];
__device__ float g_ctx [TOK * DIM];
__device__ int   g_rowmax_i;
__device__ int   g_colmax_i;

// ---------------- tf32 helpers ----------------
__device__ __forceinline__ uint32_t f2tf(float f) {
    uint32_t u;
    asm("cvt.rna.tf32.f32 %0, %1;" : "=r"(u) : "f"(f));
    return u;
}

__device__ __forceinline__ void mma_tf32(float* c, const uint32_t* a, const uint32_t* b) {
    asm volatile(
        "mma.sync.aligned.m16n8k8.row.col.f32.tf32.tf32.f32 "
        "{%0,%1,%2,%3}, {%4,%5,%6,%7}, {%8,%9}, {%0,%1,%2,%3};"
        : "+f"(c[0]), "+f"(c[1]), "+f"(c[2]), "+f"(c[3])
        : "r"(a[0]), "r"(a[1]), "r"(a[2]), "r"(a[3]), "r"(b[0]), "r"(b[1]));
}

// ---------------- batched tf32 tensor-core GEMM ----------------
// C[z] = alpha * A[z] @ op(B[z]) (+ bias[col]) (+ rscale * resid[z])
// A is [M][K] row-major (lda); B is [K][N] (ldb) or, if TB, [N][K] (ldb).
// Every operand addressed as base + zb*s1 + zh*s2, with z = zb*H + zh.
// Requires M%BM==0, N%BN==0, K%BK==0.
template<int BM, int BN, int BK, int WM, int WN, bool TB>
__global__ __launch_bounds__(32 * WM * WN, 2)
void tgemm(const float* __restrict__ A, const float* __restrict__ Bm, float* __restrict__ C,
           int lda, int ldb, int ldc, int Kn,
           long sA1, long sA2, long sB1, long sB2, long sC1, long sC2,
           float alpha, const float* __restrict__ bias,
           const float* __restrict__ resid, float rscale, long sR1, long sR2)
{
    constexpr int NT  = 32 * WM * WN;          // threads
    constexpr int SA  = BK + 4;                // As row stride (words) -> conflict-free
    constexpr int SB  = TB ? (BK + 4) : (BN + 8);
    constexpr int MT  = BM / WM / 16;          // m16 tiles per warp
    constexpr int NTl = BN / WN / 8;           // n8 tiles per warp
    constexpr int LA  = BM * BK / (4 * NT);    // float4 loads/thread for A slab
    constexpr int LB  = BN * BK / (4 * NT);    // float4 loads/thread for B slab

    const int zb = blockIdx.z / H;
    const int zh = blockIdx.z % H;
    A  += zb * sA1 + zh * sA2;
    Bm += zb * sB1 + zh * sB2;
    C  += zb * sC1 + zh * sC2;
    if (resid) resid += zb * sR1 + zh * sR2;

    __shared__ __align__(16) uint32_t As[BM * SA];
    __shared__ __align__(16) uint32_t Bs[(TB ? BN : BK) * SB];

    const int tid  = threadIdx.x;
    const int lane = tid & 31;
    const int warp = tid >> 5;
    const int wm   = warp / WN;
    const int wn   = warp % WN;
    const int m_woff = wm * (BM / WM);
    const int n_woff = wn * (BN / WN);
    const int row0 = blockIdx.y * BM;
    const int col0 = blockIdx.x * BN;
    const int g4   = lane >> 2;       // 0..7
    const int t4   = lane & 3;        // 0..3

    // loader coordinates (k-contiguous float4 for A and TB-B; n-contiguous for non-TB B)
    int rA[LA], cA[LA];
#pragma unroll
    for (int i = 0; i < LA; i++) {
        const int idx = tid + i * NT;
        rA[i] = idx / (BK / 4);
        cA[i] = (idx % (BK / 4)) * 4;
    }
    int rB[LB], cB[LB];
#pragma unroll
    for (int i = 0; i < LB; i++) {
        const int idx = tid + i * NT;
        if (TB) { rB[i] = idx / (BK / 4); cB[i] = (idx % (BK / 4)) * 4; }
        else    { rB[i] = idx / (BN / 4); cB[i] = (idx % (BN / 4)) * 4; }
    }

    float4 pa[LA], pb[LB];
    auto loadG = [&](int k0) {
#pragma unroll
        for (int i = 0; i < LA; i++)
            pa[i] = *reinterpret_cast<const float4*>(A + (long)(row0 + rA[i]) * lda + k0 + cA[i]);
#pragma unroll
        for (int i = 0; i < LB; i++) {
            if (TB) pb[i] = *reinterpret_cast<const float4*>(Bm + (long)(col0 + rB[i]) * ldb + k0 + cB[i]);
            else    pb[i] = *reinterpret_cast<const float4*>(Bm + (long)(k0 + rB[i]) * ldb + col0 + cB[i]);
        }
    };
    auto storeS = [&]() {
#pragma unroll
        for (int i = 0; i < LA; i++) {
            uint4 t = { f2tf(pa[i].x), f2tf(pa[i].y), f2tf(pa[i].z), f2tf(pa[i].w) };
            *reinterpret_cast<uint4*>(&As[rA[i] * SA + cA[i]]) = t;
        }
#pragma unroll
        for (int i = 0; i < LB; i++) {
            uint4 t = { f2tf(pb[i].x), f2tf(pb[i].y), f2tf(pb[i].z), f2tf(pb[i].w) };
            *reinterpret_cast<uint4*>(&Bs[rB[i] * SB + cB[i]]) = t;
        }
    };

    float acc[MT][NTl][4];
#pragma unroll
    for (int i = 0; i < MT; i++)
#pragma unroll
        for (int j = 0; j < NTl; j++)
#pragma unroll
            for (int q = 0; q < 4; q++) acc[i][j][q] = 0.f;

    loadG(0);
    for (int k0 = 0; k0 < Kn; k0 += BK) {
        storeS();
        __syncthreads();
        if (k0 + BK < Kn) loadG(k0 + BK);
#pragma unroll
        for (int kb = 0; kb < BK; kb += 8) {
            uint32_t af[MT][4];
#pragma unroll
            for (int mt = 0; mt < MT; mt++) {
                const int rm = m_woff + mt * 16 + g4;
                const int kc = kb + t4;
                af[mt][0] = As[rm * SA + kc];
                af[mt][1] = As[(rm + 8) * SA + kc];
                af[mt][2] = As[rm * SA + kc + 4];
                af[mt][3] = As[(rm + 8) * SA + kc + 4];
            }
            uint32_t bf[NTl][2];
#pragma unroll
            for (int nt = 0; nt < NTl; nt++) {
                const int cn = n_woff + nt * 8 + g4;
                if (TB) {
                    bf[nt][0] = Bs[cn * SB + kb + t4];
                    bf[nt][1] = Bs[cn * SB + kb + t4 + 4];
                } else {
                    bf[nt][0] = Bs[(kb + t4) * SB + cn];
                    bf[nt][1] = Bs[(kb + t4 + 4) * SB + cn];
                }
            }
#pragma unroll
            for (int mt = 0; mt < MT; mt++)
#pragma unroll
                for (int nt = 0; nt < NTl; nt++)
                    mma_tf32(acc[mt][nt], af[mt], bf[nt]);
        }
        __syncthreads();
    }

    // epilogue
#pragma unroll
    for (int mt = 0; mt < MT; mt++) {
        const int r = row0 + m_woff + mt * 16 + g4;
#pragma unroll
        for (int nt = 0; nt < NTl; nt++) {
            const int c = col0 + n_woff + nt * 8 + 2 * t4;
            float v0 = alpha * acc[mt][nt][0];
            float v1 = alpha * acc[mt][nt][1];
            float v2 = alpha * acc[mt][nt][2];
            float v3 = alpha * acc[mt][nt][3];
            if (bias) { v0 += bias[c]; v1 += bias[c + 1]; v2 += bias[c]; v3 += bias[c + 1]; }
            if (resid) {
                const float2 r0 = *reinterpret_cast<const float2*>(resid + (long)r * ldc + c);
                const float2 r1 = *reinterpret_cast<const float2*>(resid + (long)(r + 8) * ldc + c);
                v0 += rscale * r0.x; v1 += rscale * r0.y;
                v2 += rscale * r1.x; v3 += rscale * r1.y;
            }
            *reinterpret_cast<float2*>(C + (long)r * ldc + c)       = make_float2(v0, v1);
            *reinterpret_cast<float2*>(C + (long)(r + 8) * ldc + c) = make_float2(v2, v3);
        }
    }
}

// ---------------- LayerNorm (one block per token) ----------------
__global__ void ln_kernel(const float* __restrict__ x, const float* __restrict__ gamma,
                          const float* __restrict__ beta, float* __restrict__ xn)
{
    const int t = blockIdx.x;
    const int tid = threadIdx.x;             // 256 threads, 2 elems each
    const float2 v = reinterpret_cast<const float2*>(x + (long)t * DIM)[tid];
    float s  = v.x + v.y;
    float ss = v.x * v.x + v.y * v.y;
#pragma unroll
    for (int o = 16; o; o >>= 1) {
        s  += __shfl_xor_sync(0xffffffffu, s,  o);
        ss += __shfl_xor_sync(0xffffffffu, ss, o);
    }
    __shared__ float sms[8], smss[8];
    __shared__ float mu_s, rs_s;
    if ((tid & 31) == 0) { sms[tid >> 5] = s; smss[tid >> 5] = ss; }
    __syncthreads();
    if (tid == 0) {
        float S = 0.f, SS = 0.f;
        for (int i = 0; i < 8; i++) { S += sms[i]; SS += smss[i]; }
        const float mu = S / DIM;
        mu_s = mu;
        rs_s = rsqrtf(SS / DIM - mu * mu + 1e-5f);
    }
    __syncthreads();
    const float mu = mu_s, rs = rs_s;
    const float2 g  = reinterpret_cast<const float2*>(gamma)[tid];
    const float2 be = reinterpret_cast<const float2*>(beta)[tid];
    float2 o;
    o.x = (v.x - mu) * rs * g.x + be.x;
    o.y = (v.y - mu) * rs * g.y + be.y;
    reinterpret_cast<float2*>(xn + (long)t * DIM)[tid] = o;
}

// ---------------- landmark means (q already scaled by dh^-0.5) ----------------
__global__ void landmark_kernel(const float* __restrict__ qkv,
                                float* __restrict__ ql, float* __restrict__ kl)
{
    const int idx = blockIdx.x * blockDim.x + threadIdx.x;   // BH*LM*DH
    if (idx >= BH * LM * DH) return;
    const int d  = idx % DH;
    const int j  = (idx / DH) % LM;
    const int bh = idx / (DH * LM);
    const int b = bh / H, h = bh % H;
    const float* base = qkv + ((long)(b * SEQ + j * LSZ)) * QKVW + h * DH + d;
    float sq = 0.f, sk = 0.f;
#pragma unroll
    for (int l = 0; l < LSZ; l++) {
        sq += base[(long)l * QKVW];
        sk += base[(long)l * QKVW + DIM];
    }
    ql[idx] = sq * (1.0f / LSZ) * 0.125f;   // includes q scale dh^-0.5
    kl[idx] = sk * (1.0f / LSZ);
}

// ---------------- softmax over rows of length 256 (1 warp / row) ----------------
__global__ void softmax256(float* __restrict__ data, int rows)
{
    const int warp = (blockIdx.x * blockDim.x + threadIdx.x) >> 5;
    const int lane = threadIdx.x & 31;
    if (warp >= rows) return;
    float* r = data + (long)warp * 256;
    float v[8];
    float mx = -1e30f;
#pragma unroll
    for (int j = 0; j < 8; j++) { v[j] = r[lane + j * 32]; mx = fmaxf(mx, v[j]); }
#pragma unroll
    for (int o = 16; o; o >>= 1) mx = fmaxf(mx, __shfl_xor_sync(0xffffffffu, mx, o));
    float s = 0.f;
#pragma unroll
    for (int j = 0; j < 8; j++) { v[j] = expf(v[j] - mx); s += v[j]; }
#pragma unroll
    for (int o = 16; o; o >>= 1) s += __shfl_xor_sync(0xffffffffu, s, o);
    const float inv = 1.0f / s;
#pragma unroll
    for (int j = 0; j < 8; j++) r[lane + j * 32] = v[j] * inv;
}

// ---------------- softmax over rows of length 4096 (1 block / row) ----------------
__global__ void softmax_wide(float* __restrict__ data)
{
    float* r = data + (long)blockIdx.x * SEQ;
    const int tid = threadIdx.x;            // 256 threads, 16 elems each
    float v[16];
    float mx = -1e30f;
#pragma unroll
    for (int j = 0; j < 16; j++) { v[j] = r[tid + j * 256]; mx = fmaxf(mx, v[j]); }
    __shared__ float sm[256];
    sm[tid] = mx; __syncthreads();
    for (int o = 128; o; o >>= 1) { if (tid < o) sm[tid] = fmaxf(sm[tid], sm[tid + o]); __syncthreads(); }
    mx = sm[0]; __syncthreads();
    float s = 0.f;
#pragma unroll
    for (int j = 0; j < 16; j++) { v[j] = expf(v[j] - mx); s += v[j]; }
    sm[tid] = s; __syncthreads();
    for (int o = 128; o; o >>= 1) { if (tid < o) sm[tid] += sm[tid + o]; __syncthreads(); }
    const float inv = 1.0f / sm[0];
#pragma unroll
    for (int j = 0; j < 16; j++) r[tid + j * 256] = v[j] * inv;
}

// ---------------- pinv helpers ----------------
__global__ void init_norms() { g_rowmax_i = 0; g_colmax_i = 0; }

__global__ void pinv_norms(const float* __restrict__ a2)
{
    const int bh = blockIdx.x, tid = threadIdx.x;   // 256 threads
    const float* X = a2 + (long)bh * LM * LM;
    float rs = 0.f, cs = 0.f;
    for (int j = 0; j < LM; j++) {
        rs += fabsf(X[(long)tid * LM + j]);
        cs += fabsf(X[(long)j * LM + tid]);
    }
    __shared__ float sm[256];
    sm[tid] = rs; __syncthreads();
    for (int o = 128; o; o >>= 1) { if (tid < o) sm[tid] = fmaxf(sm[tid], sm[tid + o]); __syncthreads(); }
    if (tid == 0) atomicMax(&g_rowmax_i, __float_as_int(sm[0]));
    __syncthreads();
    sm[tid] = cs; __syncthreads();
    for (int o = 128; o; o >>= 1) { if (tid < o) sm[tid] = fmaxf(sm[tid], sm[tid + o]); __syncthreads(); }
    if (tid == 0) atomicMax(&g_colmax_i, __float_as_int(sm[0]));
}

__global__ void pinv_z0(const float* __restrict__ a2, float* __restrict__ z)
{
    const long idx = (long)blockIdx.x * blockDim.x + threadIdx.x;
    if (idx >= (long)BH * LM * LM) return;
    const float inv = 1.0f / (__int_as_float(g_rowmax_i) * __int_as_float(g_colmax_i));
    const int j  = (int)(idx % LM);
    const int i  = (int)((idx / LM) % LM);
    const int bh = (int)(idx / ((long)LM * LM));
    z[idx] = a2[(long)bh * LM * LM + (long)j * LM + i] * inv;   // transpose * inv
}

// ---------------- depthwise conv over sequence (kernel 33) ----------------
__global__ void conv_kernel(const float* __restrict__ qkv, const float* __restrict__ w,
                            float* __restrict__ res)
{
    const int bh = blockIdx.y;
    const int b = bh / H, h = bh % H;
    const int i0 = blockIdx.x * 64;
    __shared__ float sm[96][DH];
    __shared__ float wsh[CK];
    const int tid = threadIdx.x;
    if (tid < CK) wsh[tid] = w[h * CK + tid];
    const float* vbase = qkv + 2 * DIM + h * DH + (long)b * SEQ * QKVW;
    for (int e = tid; e < 96 * DH; e += 256) {
        const int r = e / DH, d = e % DH;
        const int gi = i0 + r - 16;
        sm[r][d] = (gi >= 0 && gi < SEQ) ? vbase[(long)gi * QKVW + d] : 0.0f;
    }
    __syncthreads();
    float* rbase = res + (long)bh * SEQ * DH + (long)i0 * DH;
    for (int e = tid; e < 64 * DH; e += 256) {
        const int il = e / DH, d = e % DH;
        float s = 0.f;
#pragma unroll
        for (int t = 0; t < CK; t++) s = fmaf(sm[il + t][d], wsh[t], s);
        rbase[e] = s;
    }
}

// ---------------- reorder (b,h,n,dh) -> (b,n,h*dh) ----------------
__global__ void reorder_kernel(const float* __restrict__ outh, float* __restrict__ ctx)
{
    const long idx = (long)blockIdx.x * blockDim.x + threadIdx.x;
    if (idx >= (long)BH * SEQ * DH) return;
    const int d  = (int)(idx % DH);
    const int i  = (int)((idx / DH) % SEQ);
    const int bh = (int)(idx / ((long)DH * SEQ));
    const int b = bh / H, h = bh % H;
    ctx[((long)(b * SEQ + i)) * DIM + h * DH + d] = outh[idx];
}

// ---------------- host orchestration ----------------
extern "C" void kernel_launch(void* const* d_in, const int* in_sizes, int n_in,
                              void* d_out, int out_size)
{
    const float* x     = (const float*)d_in[0];
    const float* gamma = (const float*)d_in[1];
    const float* beta  = (const float*)d_in[2];
    const float* Wqkv  = (const float*)d_in[3];
    const float* Wout  = (const float*)d_in[4];
    const float* bout  = (const float*)d_in[5];
    const float* convw = (const float*)d_in[6];
    float* out = (float*)d_out;

    float *p_xn, *p_qkv, *p_ql, *p_kl, *p_sim1, *p_sim3, *p_a2, *p_z, *p_z2,
          *p_xz, *p_t, *p_w, *p_a3v, *p_za3v, *p_res, *p_outh, *p_ctx;
    cudaGetSymbolAddress((void**)&p_xn,   g_xn);
    cudaGetSymbolAddress((void**)&p_qkv,  g_qkv);
    cudaGetSymbolAddress((void**)&p_ql,   g_ql);
    cudaGetSymbolAddress((void**)&p_kl,   g_kl);
    cudaGetSymbolAddress((void**)&p_sim1, g_sim1);
    cudaGetSymbolAddress((void**)&p_sim3, g_sim3);
    cudaGetSymbolAddress((void**)&p_a2,   g_a2);
    cudaGetSymbolAddress((void**)&p_z,    g_z);
    cudaGetSymbolAddress((void**)&p_z2,   g_z2);
    cudaGetSymbolAddress((void**)&p_xz,   g_xz);
    cudaGetSymbolAddress((void**)&p_t,    g_t);
    cudaGetSymbolAddress((void**)&p_w,    g_w);
    cudaGetSymbolAddress((void**)&p_a3v,  g_a3v);
    cudaGetSymbolAddress((void**)&p_za3v, g_za3v);
    cudaGetSymbolAddress((void**)&p_res,  g_res);
    cudaGetSymbolAddress((void**)&p_outh, g_outh);
    cudaGetSymbolAddress((void**)&p_ctx,  g_ctx);

    const long sQKVb = (long)SEQ * QKVW;        // per-b stride in qkv view
    const long sLD_b = (long)H * LM * DH, sLD_h = (long)LM * DH;     // [bh][LM][DH]
    const long sS1_b = (long)H * SEQ * LM, sS1_h = (long)SEQ * LM;   // [bh][SEQ][LM]
    const long sS3_b = (long)H * LM * SEQ, sS3_h = (long)LM * SEQ;   // [bh][LM][SEQ]
    const long sMM_b = (long)H * LM * LM,  sMM_h = (long)LM * LM;    // [bh][LM][LM]
    const long sOH_b = (long)H * SEQ * DH, sOH_h = (long)SEQ * DH;   // [bh][SEQ][DH]

    // 1) LayerNorm
    ln_kernel<<<TOK, 256>>>(x, gamma, beta, p_xn);

    // 2) QKV projection: (16384x512) @ (512x1536)
    tgemm<128,128,16,2,4,false><<<dim3(QKVW/128, TOK/128, 1), 256>>>(
        p_xn, Wqkv, p_qkv, DIM, QKVW, QKVW, DIM,
        0,0, 0,0, 0,0, 1.0f, nullptr, nullptr, 0.f, 0,0);

    // 3) landmarks
    landmark_kernel<<<(BH*LM*DH)/256, 256>>>(p_qkv, p_ql, p_kl);

    // 4) sim1 = scale * q @ k_l^T   (batched, q is a view into qkv)
    tgemm<128,128,16,2,4,true><<<dim3(LM/128, SEQ/128, BH), 256>>>(
        p_qkv, p_kl, p_sim1, QKVW, DH, LM, DH,
        sQKVb, DH, sLD_b, sLD_h, sS1_b, sS1_h, 0.125f, nullptr, nullptr, 0.f, 0,0);

    // 5) sim2 = q_l @ k_l^T
    tgemm<128,128,16,2,4,true><<<dim3(LM/128, LM/128, BH), 256>>>(
        p_ql, p_kl, p_a2, DH, DH, LM, DH,
        sLD_b, sLD_h, sLD_b, sLD_h, sMM_b, sMM_h, 1.0f, nullptr, nullptr, 0.f, 0,0);

    // 6) sim3 = q_l @ k^T   (k is a view into qkv at +DIM)
    tgemm<128,128,16,2,4,true><<<dim3(SEQ/128, LM/128, BH), 256>>>(
        p_ql, p_qkv + DIM, p_sim3, DH, QKVW, SEQ, DH,
        sLD_b, sLD_h, sQKVb, DH, sS3_b, sS3_h, 1.0f, nullptr, nullptr, 0.f, 0,0);

    // 7) softmaxes
    softmax256<<<(BH*SEQ)/8, 256>>>(p_sim1, BH*SEQ);   // a1
    softmax256<<<(BH*LM)/8, 256>>>(p_a2, BH*LM);       // a2
    softmax_wide<<<BH*LM, 256>>>(p_sim3);              // a3

    // 8) pinv(a2) via Newton-Schulz (aI-minus passes folded into GEMM epilogues)
    init_norms<<<1,1>>>();
    pinv_norms<<<BH, 256>>>(p_a2);
    pinv_z0<<<(BH*LM*LM)/256, 256>>>(p_a2, p_z);
    for (int it = 0; it < 6; it++) {
        float* zin  = (it & 1) ? p_z2 : p_z;
        float* zout = (it & 1) ? p_z  : p_z2;
        // xz = a2 @ z
        tgemm<128,128,16,2,4,false><<<dim3(2,2,BH), 256>>>(
            p_a2, zin, p_xz, LM, LM, LM, LM,
            sMM_b, sMM_h, sMM_b, sMM_h, sMM_b, sMM_h, 1.0f, nullptr, nullptr, 0.f, 0,0);
        // w = xz @ (7I - xz) = -xz@xz + 7*xz
        tgemm<128,128,16,2,4,false><<<dim3(2,2,BH), 256>>>(
            p_xz, p_xz, p_w, LM, LM, LM, LM,
            sMM_b, sMM_h, sMM_b, sMM_h, sMM_b, sMM_h, -1.0f, nullptr, p_xz, 7.0f, sMM_b, sMM_h);
        // u = xz @ (15I - w) = -xz@w + 15*xz
        tgemm<128,128,16,2,4,false><<<dim3(2,2,BH), 256>>>(
            p_xz, p_w, p_t, LM, LM, LM, LM,
            sMM_b, sMM_h, sMM_b, sMM_h, sMM_b, sMM_h, -1.0f, nullptr, p_xz, 15.0f, sMM_b, sMM_h);
        // z' = 0.25 * z @ (13I - u) = -0.25*z@u + 3.25*z
        tgemm<128,128,16,2,4,false><<<dim3(2,2,BH), 256>>>(
            zin, p_t, zout, LM, LM, LM, LM,
            sMM_b, sMM_h, sMM_b, sMM_h, sMM_b, sMM_h, -0.25f, nullptr, zin, 3.25f, sMM_b, sMM_h);
    }
    // final z in p_z (6 swaps)

    // 9) a3v = a3 @ v   (v is a view into qkv at +2*DIM)
    tgemm<128,64,16,4,2,false><<<dim3(1, LM/128, BH), 256>>>(
        p_sim3, p_qkv + 2*DIM, p_a3v, SEQ, QKVW, DH, SEQ,
        sS3_b, sS3_h, sQKVb, DH, sLD_b, sLD_h, 1.0f, nullptr, nullptr, 0.f, 0,0);

    // 10) za3v = z @ a3v   (reassociated: (a1@z)@(a3@v) == a1@(z@(a3@v)))
    tgemm<128,64,16,4,2,false><<<dim3(1, LM/128, BH), 256>>>(
        p_z, p_a3v, p_za3v, LM, DH, DH, LM,
        sMM_b, sMM_h, sLD_b, sLD_h, sLD_b, sLD_h, 1.0f, nullptr, nullptr, 0.f, 0,0);

    // 11) depthwise conv residual over v
    conv_kernel<<<dim3(SEQ/64, BH), 256>>>(p_qkv, convw, p_res);

    // 12) outh = a1 @ za3v + conv_res
    tgemm<128,64,16,4,2,false><<<dim3(1, SEQ/128, BH), 256>>>(
        p_sim1, p_za3v, p_outh, LM, DH, DH, LM,
        sS1_b, sS1_h, sLD_b, sLD_h, sOH_b, sOH_h, 1.0f, nullptr, p_res, 1.0f, sOH_b, sOH_h);

    // 13) reorder to (b, n, dim)
    reorder_kernel<<<(BH*SEQ*DH)/256, 256>>>(p_outh, p_ctx);

    // 14) final: out = ctx @ W_out + b_out + x
    tgemm<128,128,16,2,4,false><<<dim3(DIM/128, TOK/128, 1), 256>>>(
        p_ctx, Wout, out, DIM, DIM, DIM, DIM,
        0,0, 0,0, 0,0, 1.0f, bout, x, 1.0f, 0,0);
}

// round 6
// speedup vs baseline: 3.5086x; 1.2250x over previous
#include <cuda_runtime.h>
#include <cstdint>

// ---------------- problem constants ----------------
constexpr int B    = 4;
constexpr int SEQ  = 4096;
constexpr int DIM  = 512;
constexpr int H    = 8;
constexpr int DH   = 64;     // DIM / H
constexpr int LM   = 256;    // landmarks
constexpr int LSZ  = 16;     // SEQ / LM
constexpr int BH   = B * H;  // 32
constexpr int CK   = 33;     // conv kernel
constexpr int TOK  = B * SEQ;        // 16384
constexpr int QKVW = 3 * DIM;        // 1536

// ---------------- scratch (static device memory; no allocations) ----------------
__device__ float g_xn  [TOK * DIM];
__device__ float g_qkv [(long)TOK * QKVW];
__device__ float g_ql  [BH * LM * DH];
__device__ float g_kl  [BH * LM * DH];
__device__ float g_sim1[(long)BH * SEQ * LM];   // -> a1 (softmax fused in epilogue)
__device__ float g_a2  [BH * LM * LM];
__device__ float g_z   [BH * LM * LM];
__device__ float g_z2  [BH * LM * LM];
__device__ float g_xz  [BH * LM * LM];
__device__ float g_t   [BH * LM * LM];
__device__ float g_w   [BH * LM * LM];
__device__ float g_a3v [BH * LM * DH];
__device__ float g_za3v[BH * LM * DH];
__device__ float g_res [(long)BH * SEQ * DH];
__device__ float g_ctx [TOK * DIM];
__device__ int   g_rowmax_i;
__device__ int   g_colmax_i;

// ---------------- tf32 helpers ----------------
__device__ __forceinline__ uint32_t f2tf(float f) {
    uint32_t u;
    asm("cvt.rna.tf32.f32 %0, %1;" : "=r"(u) : "f"(f));
    return u;
}

__device__ __forceinline__ void mma_tf32(float* c, const uint32_t* a, const uint32_t* b) {
    asm volatile(
        "mma.sync.aligned.m16n8k8.row.col.f32.tf32.tf32.f32 "
        "{%0,%1,%2,%3}, {%4,%5,%6,%7}, {%8,%9}, {%0,%1,%2,%3};"
        : "+f"(c[0]), "+f"(c[1]), "+f"(c[2]), "+f"(c[3])
        : "r"(a[0]), "r"(a[1]), "r"(a[2]), "r"(a[3]), "r"(b[0]), "r"(b[1]));
}

// ---------------- batched tf32 tensor-core GEMM ----------------
// C[z] = alpha * A[z] @ op(B[z]) (+ bias[col]) (+ rscale * resid[z] with row-stride ldr)
template<int BM, int BN, int BK, int WM, int WN, bool TB>
__global__ __launch_bounds__(32 * WM * WN, 2)
void tgemm(const float* __restrict__ A, const float* __restrict__ Bm, float* __restrict__ C,
           int lda, int ldb, int ldc, int Kn,
           long sA1, long sA2, long sB1, long sB2, long sC1, long sC2,
           float alpha, const float* __restrict__ bias,
           const float* __restrict__ resid, float rscale, int ldr, long sR1, long sR2)
{
    constexpr int NT  = 32 * WM * WN;
    constexpr int SA  = BK + 4;
    constexpr int SB  = TB ? (BK + 4) : (BN + 8);
    constexpr int MT  = BM / WM / 16;
    constexpr int NTl = BN / WN / 8;
    constexpr int LA  = BM * BK / (4 * NT);
    constexpr int LB  = BN * BK / (4 * NT);

    const int zb = blockIdx.z / H;
    const int zh = blockIdx.z % H;
    A  += zb * sA1 + zh * sA2;
    Bm += zb * sB1 + zh * sB2;
    C  += zb * sC1 + zh * sC2;
    if (resid) resid += zb * sR1 + zh * sR2;

    __shared__ __align__(16) uint32_t As[BM * SA];
    __shared__ __align__(16) uint32_t Bs[(TB ? BN : BK) * SB];

    const int tid  = threadIdx.x;
    const int lane = tid & 31;
    const int warp = tid >> 5;
    const int wm   = warp / WN;
    const int wn   = warp % WN;
    const int m_woff = wm * (BM / WM);
    const int n_woff = wn * (BN / WN);
    const int row0 = blockIdx.y * BM;
    const int col0 = blockIdx.x * BN;
    const int g4   = lane >> 2;
    const int t4   = lane & 3;

    int rA[LA], cA[LA];
#pragma unroll
    for (int i = 0; i < LA; i++) {
        const int idx = tid + i * NT;
        rA[i] = idx / (BK / 4);
        cA[i] = (idx % (BK / 4)) * 4;
    }
    int rB[LB], cB[LB];
#pragma unroll
    for (int i = 0; i < LB; i++) {
        const int idx = tid + i * NT;
        if (TB) { rB[i] = idx / (BK / 4); cB[i] = (idx % (BK / 4)) * 4; }
        else    { rB[i] = idx / (BN / 4); cB[i] = (idx % (BN / 4)) * 4; }
    }

    float4 pa[LA], pb[LB];
    auto loadG = [&](int k0) {
#pragma unroll
        for (int i = 0; i < LA; i++)
            pa[i] = *reinterpret_cast<const float4*>(A + (long)(row0 + rA[i]) * lda + k0 + cA[i]);
#pragma unroll
        for (int i = 0; i < LB; i++) {
            if (TB) pb[i] = *reinterpret_cast<const float4*>(Bm + (long)(col0 + rB[i]) * ldb + k0 + cB[i]);
            else    pb[i] = *reinterpret_cast<const float4*>(Bm + (long)(k0 + rB[i]) * ldb + col0 + cB[i]);
        }
    };
    auto storeS = [&]() {
#pragma unroll
        for (int i = 0; i < LA; i++) {
            uint4 t = { f2tf(pa[i].x), f2tf(pa[i].y), f2tf(pa[i].z), f2tf(pa[i].w) };
            *reinterpret_cast<uint4*>(&As[rA[i] * SA + cA[i]]) = t;
        }
#pragma unroll
        for (int i = 0; i < LB; i++) {
            uint4 t = { f2tf(pb[i].x), f2tf(pb[i].y), f2tf(pb[i].z), f2tf(pb[i].w) };
            *reinterpret_cast<uint4*>(&Bs[rB[i] * SB + cB[i]]) = t;
        }
    };

    float acc[MT][NTl][4];
#pragma unroll
    for (int i = 0; i < MT; i++)
#pragma unroll
        for (int j = 0; j < NTl; j++)
#pragma unroll
            for (int q = 0; q < 4; q++) acc[i][j][q] = 0.f;

    loadG(0);
    for (int k0 = 0; k0 < Kn; k0 += BK) {
        storeS();
        __syncthreads();
        if (k0 + BK < Kn) loadG(k0 + BK);
#pragma unroll
        for (int kb = 0; kb < BK; kb += 8) {
            uint32_t af[MT][4];
#pragma unroll
            for (int mt = 0; mt < MT; mt++) {
                const int rm = m_woff + mt * 16 + g4;
                const int kc = kb + t4;
                af[mt][0] = As[rm * SA + kc];
                af[mt][1] = As[(rm + 8) * SA + kc];
                af[mt][2] = As[rm * SA + kc + 4];
                af[mt][3] = As[(rm + 8) * SA + kc + 4];
            }
#pragma unroll
            for (int nt = 0; nt < NTl; nt++) {
                const int cn = n_woff + nt * 8 + g4;
                uint32_t bf[2];
                if (TB) {
                    bf[0] = Bs[cn * SB + kb + t4];
                    bf[1] = Bs[cn * SB + kb + t4 + 4];
                } else {
                    bf[0] = Bs[(kb + t4) * SB + cn];
                    bf[1] = Bs[(kb + t4 + 4) * SB + cn];
                }
#pragma unroll
                for (int mt = 0; mt < MT; mt++)
                    mma_tf32(acc[mt][nt], af[mt], bf);
            }
        }
        __syncthreads();
    }

#pragma unroll
    for (int mt = 0; mt < MT; mt++) {
        const int r = row0 + m_woff + mt * 16 + g4;
#pragma unroll
        for (int nt = 0; nt < NTl; nt++) {
            const int c = col0 + n_woff + nt * 8 + 2 * t4;
            float v0 = alpha * acc[mt][nt][0];
            float v1 = alpha * acc[mt][nt][1];
            float v2 = alpha * acc[mt][nt][2];
            float v3 = alpha * acc[mt][nt][3];
            if (bias) { v0 += bias[c]; v1 += bias[c + 1]; v2 += bias[c]; v3 += bias[c + 1]; }
            if (resid) {
                const float2 r0 = *reinterpret_cast<const float2*>(resid + (long)r * ldr + c);
                const float2 r1 = *reinterpret_cast<const float2*>(resid + (long)(r + 8) * ldr + c);
                v0 += rscale * r0.x; v1 += rscale * r0.y;
                v2 += rscale * r1.x; v3 += rscale * r1.y;
            }
            *reinterpret_cast<float2*>(C + (long)r * ldc + c)       = make_float2(v0, v1);
            *reinterpret_cast<float2*>(C + (long)(r + 8) * ldc + c) = make_float2(v2, v3);
        }
    }
}

// ---------------- sim1 GEMM with fused row softmax (N=256 in one CTA) ----------
// a1 = softmax(0.125 * q @ kl^T).  BM=128, BN=256, BK=16, 512 threads (WM=4,WN=4).
__global__ __launch_bounds__(512, 1)
void tgemm_sm1(const float* __restrict__ qkv, const float* __restrict__ kl,
               float* __restrict__ a1)
{
    constexpr int SA = 20, SB = 20;
    const int zb = blockIdx.z / H, zh = blockIdx.z % H;
    const float* A  = qkv + (long)zb * SEQ * QKVW + (long)zh * DH;
    const float* Bp = kl + (long)blockIdx.z * LM * DH;
    float* Cp = a1 + (long)blockIdx.z * SEQ * LM;

    __shared__ __align__(16) uint32_t As[128 * SA];
    __shared__ __align__(16) uint32_t Bs[256 * SB];
    __shared__ float red[128][4];

    const int tid = threadIdx.x, lane = tid & 31, warp = tid >> 5;
    const int wm = warp >> 2, wn = warp & 3;
    const int m_woff = wm * 32, n_woff = wn * 64;
    const int row0 = blockIdx.y * 128;
    const int g4 = lane >> 2, t4 = lane & 3;

    const int rA = tid >> 2, cA = (tid & 3) << 2;        // A loader (1 float4)
    const int rB0 = tid >> 2, rB1 = (tid + 512) >> 2;    // B loader (2 float4)

    float4 pa, pb0, pb1;
    auto loadG = [&](int k0) {
        pa  = *reinterpret_cast<const float4*>(A + (long)(row0 + rA) * QKVW + k0 + cA);
        pb0 = *reinterpret_cast<const float4*>(Bp + (long)rB0 * DH + k0 + cA);
        pb1 = *reinterpret_cast<const float4*>(Bp + (long)rB1 * DH + k0 + cA);
    };
    auto storeS = [&]() {
        uint4 ta = { f2tf(pa.x), f2tf(pa.y), f2tf(pa.z), f2tf(pa.w) };
        *reinterpret_cast<uint4*>(&As[rA * SA + cA]) = ta;
        uint4 t0 = { f2tf(pb0.x), f2tf(pb0.y), f2tf(pb0.z), f2tf(pb0.w) };
        *reinterpret_cast<uint4*>(&Bs[rB0 * SB + cA]) = t0;
        uint4 t1 = { f2tf(pb1.x), f2tf(pb1.y), f2tf(pb1.z), f2tf(pb1.w) };
        *reinterpret_cast<uint4*>(&Bs[rB1 * SB + cA]) = t1;
    };

    float acc[2][8][4];
#pragma unroll
    for (int i = 0; i < 2; i++)
#pragma unroll
        for (int j = 0; j < 8; j++)
#pragma unroll
            for (int q = 0; q < 4; q++) acc[i][j][q] = 0.f;

    loadG(0);
    for (int k0 = 0; k0 < DH; k0 += 16) {
        storeS();
        __syncthreads();
        if (k0 + 16 < DH) loadG(k0 + 16);
#pragma unroll
        for (int kb = 0; kb < 16; kb += 8) {
            uint32_t af[2][4];
#pragma unroll
            for (int mt = 0; mt < 2; mt++) {
                const int rm = m_woff + mt * 16 + g4;
                const int kc = kb + t4;
                af[mt][0] = As[rm * SA + kc];
                af[mt][1] = As[(rm + 8) * SA + kc];
                af[mt][2] = As[rm * SA + kc + 4];
                af[mt][3] = As[(rm + 8) * SA + kc + 4];
            }
#pragma unroll
            for (int nt = 0; nt < 8; nt++) {
                const int cn = n_woff + nt * 8 + g4;
                uint32_t bf[2] = { Bs[cn * SB + kb + t4], Bs[cn * SB + kb + t4 + 4] };
#pragma unroll
                for (int mt = 0; mt < 2; mt++) mma_tf32(acc[mt][nt], af[mt], bf);
            }
        }
        __syncthreads();
    }

    // ---- fused softmax over full rows (N=256) ----
#pragma unroll
    for (int mt = 0; mt < 2; mt++)
#pragma unroll
        for (int nt = 0; nt < 8; nt++)
#pragma unroll
            for (int q = 0; q < 4; q++) acc[mt][nt][q] *= 0.125f;

    float lmax[2][2] = { {-1e30f, -1e30f}, {-1e30f, -1e30f} };
#pragma unroll
    for (int mt = 0; mt < 2; mt++)
#pragma unroll
        for (int nt = 0; nt < 8; nt++)
#pragma unroll
            for (int q = 0; q < 4; q++)
                lmax[mt][q >> 1] = fmaxf(lmax[mt][q >> 1], acc[mt][nt][q]);
#pragma unroll
    for (int o = 1; o <= 2; o <<= 1)
#pragma unroll
        for (int mt = 0; mt < 2; mt++)
#pragma unroll
            for (int hh = 0; hh < 2; hh++)
                lmax[mt][hh] = fmaxf(lmax[mt][hh], __shfl_xor_sync(0xffffffffu, lmax[mt][hh], o));
    if (t4 == 0)
#pragma unroll
        for (int mt = 0; mt < 2; mt++)
#pragma unroll
            for (int hh = 0; hh < 2; hh++)
                red[m_woff + mt * 16 + hh * 8 + g4][wn] = lmax[mt][hh];
    __syncthreads();
    float rmax[2][2];
#pragma unroll
    for (int mt = 0; mt < 2; mt++)
#pragma unroll
        for (int hh = 0; hh < 2; hh++) {
            const int rb = m_woff + mt * 16 + hh * 8 + g4;
            rmax[mt][hh] = fmaxf(fmaxf(red[rb][0], red[rb][1]), fmaxf(red[rb][2], red[rb][3]));
        }
    __syncthreads();
    float lsum[2][2] = { {0.f, 0.f}, {0.f, 0.f} };
#pragma unroll
    for (int mt = 0; mt < 2; mt++)
#pragma unroll
        for (int nt = 0; nt < 8; nt++)
#pragma unroll
            for (int q = 0; q < 4; q++) {
                const float e = expf(acc[mt][nt][q] - rmax[mt][q >> 1]);
                acc[mt][nt][q] = e;
                lsum[mt][q >> 1] += e;
            }
#pragma unroll
    for (int o = 1; o <= 2; o <<= 1)
#pragma unroll
        for (int mt = 0; mt < 2; mt++)
#pragma unroll
            for (int hh = 0; hh < 2; hh++)
                lsum[mt][hh] += __shfl_xor_sync(0xffffffffu, lsum[mt][hh], o);
    if (t4 == 0)
#pragma unroll
        for (int mt = 0; mt < 2; mt++)
#pragma unroll
            for (int hh = 0; hh < 2; hh++)
                red[m_woff + mt * 16 + hh * 8 + g4][wn] = lsum[mt][hh];
    __syncthreads();
    float rinv[2][2];
#pragma unroll
    for (int mt = 0; mt < 2; mt++)
#pragma unroll
        for (int hh = 0; hh < 2; hh++) {
            const int rb = m_woff + mt * 16 + hh * 8 + g4;
            rinv[mt][hh] = 1.0f / (red[rb][0] + red[rb][1] + red[rb][2] + red[rb][3]);
        }
#pragma unroll
    for (int mt = 0; mt < 2; mt++) {
        const int r = row0 + m_woff + mt * 16 + g4;
#pragma unroll
        for (int nt = 0; nt < 8; nt++) {
            const int c = n_woff + nt * 8 + 2 * t4;
            *reinterpret_cast<float2*>(Cp + (long)r * LM + c) =
                make_float2(acc[mt][nt][0] * rinv[mt][0], acc[mt][nt][1] * rinv[mt][0]);
            *reinterpret_cast<float2*>(Cp + (long)(r + 8) * LM + c) =
                make_float2(acc[mt][nt][2] * rinv[mt][1], acc[mt][nt][3] * rinv[mt][1]);
        }
    }
}

// ---------------- flash-style fused a3v = softmax(q_l @ k^T) @ v -----------------
// Grid (LM/64, BH), 256 threads. Online softmax over SEQ in tiles of 128.
constexpr int FL_TS = 128;
constexpr int FL_SMEM_WORDS = 64 * 68 + 128 * 68 + 128 * 72 + 64 * 132 + 64 * 4;

__global__ __launch_bounds__(256, 1)
void flash_a3v(const float* __restrict__ ql, const float* __restrict__ qkv,
               float* __restrict__ a3v)
{
    extern __shared__ uint32_t dsm[];
    uint32_t* Qs = dsm;                       // [64][68]
    uint32_t* Ks = Qs + 64 * 68;              // [128][68]  (TB layout: k-row x dh)
    uint32_t* Vs = Ks + 128 * 68;             // [128][72]  (k-row x dh)
    uint32_t* Ps = Vs + 128 * 72;             // [64][132]
    float*    red = (float*)(Ps + 64 * 132);  // [64][4]

    const int bh = blockIdx.y;
    const int b = bh / H, h = bh % H;
    const int row0 = blockIdx.x * 64;
    const int tid = threadIdx.x, lane = tid & 31, warp = tid >> 5;
    const int wm = warp >> 2, wn = warp & 3;
    const int g4 = lane >> 2, t4 = lane & 3;
    const int m_woff = wm * 32;

    const float* kbase = qkv + DIM     + (long)b * SEQ * QKVW + h * DH;
    const float* vbase = qkv + 2 * DIM + (long)b * SEQ * QKVW + h * DH;
    const float* qbase = ql + (long)bh * LM * DH + (long)row0 * DH;

    // load Q tile (64 x 64) once
#pragma unroll
    for (int i = 0; i < 4; i++) {
        const int idx = tid + i * 256;
        const int r = idx >> 4, c = (idx & 15) << 2;
        const float4 v = *reinterpret_cast<const float4*>(qbase + (long)r * DH + c);
        uint4 t = { f2tf(v.x), f2tf(v.y), f2tf(v.z), f2tf(v.w) };
        *reinterpret_cast<uint4*>(&Qs[r * 68 + c]) = t;
    }

    float accO[2][2][4];
#pragma unroll
    for (int mt = 0; mt < 2; mt++)
#pragma unroll
        for (int nt = 0; nt < 2; nt++)
#pragma unroll
            for (int q = 0; q < 4; q++) accO[mt][nt][q] = 0.f;
    float mrow[2][2] = { {-1e30f, -1e30f}, {-1e30f, -1e30f} };
    float srow[2][2] = { {0.f, 0.f}, {0.f, 0.f} };

    for (int kb0 = 0; kb0 < SEQ; kb0 += FL_TS) {
        __syncthreads();   // protect Ks/Vs/Ps rewrite
        // load K and V tiles (128 x 64 each)
#pragma unroll
        for (int i = 0; i < 8; i++) {
            const int idx = tid + i * 256;
            const int r = idx >> 4, c = (idx & 15) << 2;
            const float4 kv = *reinterpret_cast<const float4*>(kbase + (long)(kb0 + r) * QKVW + c);
            uint4 tk = { f2tf(kv.x), f2tf(kv.y), f2tf(kv.z), f2tf(kv.w) };
            *reinterpret_cast<uint4*>(&Ks[r * 68 + c]) = tk;
            const float4 vv = *reinterpret_cast<const float4*>(vbase + (long)(kb0 + r) * QKVW + c);
            uint4 tv = { f2tf(vv.x), f2tf(vv.y), f2tf(vv.z), f2tf(vv.w) };
            *reinterpret_cast<uint4*>(&Vs[r * 72 + c]) = tv;
        }
        __syncthreads();

        // S = Q @ Ktile^T : 64x128, K=64
        float accS[2][4][4];
#pragma unroll
        for (int mt = 0; mt < 2; mt++)
#pragma unroll
            for (int nt = 0; nt < 4; nt++)
#pragma unroll
                for (int q = 0; q < 4; q++) accS[mt][nt][q] = 0.f;
#pragma unroll
        for (int kb = 0; kb < 64; kb += 8) {
            uint32_t af[2][4];
#pragma unroll
            for (int mt = 0; mt < 2; mt++) {
                const int rm = m_woff + mt * 16 + g4;
                af[mt][0] = Qs[rm * 68 + kb + t4];
                af[mt][1] = Qs[(rm + 8) * 68 + kb + t4];
                af[mt][2] = Qs[rm * 68 + kb + t4 + 4];
                af[mt][3] = Qs[(rm + 8) * 68 + kb + t4 + 4];
            }
#pragma unroll
            for (int nt = 0; nt < 4; nt++) {
                const int cn = wn * 32 + nt * 8 + g4;
                uint32_t bf[2] = { Ks[cn * 68 + kb + t4], Ks[cn * 68 + kb + t4 + 4] };
#pragma unroll
                for (int mt = 0; mt < 2; mt++) mma_tf32(accS[mt][nt], af[mt], bf);
            }
        }

        // chunk max
        float cmax[2][2] = { {-1e30f, -1e30f}, {-1e30f, -1e30f} };
#pragma unroll
        for (int mt = 0; mt < 2; mt++)
#pragma unroll
            for (int nt = 0; nt < 4; nt++)
#pragma unroll
                for (int q = 0; q < 4; q++)
                    cmax[mt][q >> 1] = fmaxf(cmax[mt][q >> 1], accS[mt][nt][q]);
#pragma unroll
        for (int o = 1; o <= 2; o <<= 1)
#pragma unroll
            for (int mt = 0; mt < 2; mt++)
#pragma unroll
                for (int hh = 0; hh < 2; hh++)
                    cmax[mt][hh] = fmaxf(cmax[mt][hh], __shfl_xor_sync(0xffffffffu, cmax[mt][hh], o));
        if (t4 == 0)
#pragma unroll
            for (int mt = 0; mt < 2; mt++)
#pragma unroll
                for (int hh = 0; hh < 2; hh++)
                    red[(m_woff + mt * 16 + hh * 8 + g4) * 4 + wn] = cmax[mt][hh];
        __syncthreads();
        float cscale[2][2], mnew[2][2];
#pragma unroll
        for (int mt = 0; mt < 2; mt++)
#pragma unroll
            for (int hh = 0; hh < 2; hh++) {
                const int rb = (m_woff + mt * 16 + hh * 8 + g4) * 4;
                const float cm = fmaxf(fmaxf(red[rb], red[rb + 1]), fmaxf(red[rb + 2], red[rb + 3]));
                mnew[mt][hh] = fmaxf(mrow[mt][hh], cm);
                cscale[mt][hh] = expf(mrow[mt][hh] - mnew[mt][hh]);
                mrow[mt][hh] = mnew[mt][hh];
            }
        __syncthreads();   // red reads done before sum overwrite

        // exponentiate + chunk sums
        float lsum[2][2] = { {0.f, 0.f}, {0.f, 0.f} };
#pragma unroll
        for (int mt = 0; mt < 2; mt++)
#pragma unroll
            for (int nt = 0; nt < 4; nt++)
#pragma unroll
                for (int q = 0; q < 4; q++) {
                    const float e = expf(accS[mt][nt][q] - mnew[mt][q >> 1]);
                    accS[mt][nt][q] = e;
                    lsum[mt][q >> 1] += e;
                }
#pragma unroll
        for (int o = 1; o <= 2; o <<= 1)
#pragma unroll
            for (int mt = 0; mt < 2; mt++)
#pragma unroll
                for (int hh = 0; hh < 2; hh++)
                    lsum[mt][hh] += __shfl_xor_sync(0xffffffffu, lsum[mt][hh], o);
        if (t4 == 0)
#pragma unroll
            for (int mt = 0; mt < 2; mt++)
#pragma unroll
                for (int hh = 0; hh < 2; hh++)
                    red[(m_woff + mt * 16 + hh * 8 + g4) * 4 + wn] = lsum[mt][hh];
        __syncthreads();
#pragma unroll
        for (int mt = 0; mt < 2; mt++)
#pragma unroll
            for (int hh = 0; hh < 2; hh++) {
                const int rb = (m_woff + mt * 16 + hh * 8 + g4) * 4;
                const float cs = red[rb] + red[rb + 1] + red[rb + 2] + red[rb + 3];
                srow[mt][hh] = srow[mt][hh] * cscale[mt][hh] + cs;
            }
        // rescale O
#pragma unroll
        for (int mt = 0; mt < 2; mt++)
#pragma unroll
            for (int nt = 0; nt < 2; nt++)
#pragma unroll
                for (int q = 0; q < 4; q++) accO[mt][nt][q] *= cscale[mt][q >> 1];

        // store P to smem (tf32)
#pragma unroll
        for (int mt = 0; mt < 2; mt++) {
            const int r = m_woff + mt * 16 + g4;
#pragma unroll
            for (int nt = 0; nt < 4; nt++) {
                const int cb = wn * 32 + nt * 8 + 2 * t4;
                Ps[r * 132 + cb]           = f2tf(accS[mt][nt][0]);
                Ps[r * 132 + cb + 1]       = f2tf(accS[mt][nt][1]);
                Ps[(r + 8) * 132 + cb]     = f2tf(accS[mt][nt][2]);
                Ps[(r + 8) * 132 + cb + 1] = f2tf(accS[mt][nt][3]);
            }
        }
        __syncthreads();

        // O += P @ Vtile : 64x64, K=128
#pragma unroll
        for (int kb = 0; kb < 128; kb += 8) {
            uint32_t af[2][4];
#pragma unroll
            for (int mt = 0; mt < 2; mt++) {
                const int rm = m_woff + mt * 16 + g4;
                af[mt][0] = Ps[rm * 132 + kb + t4];
                af[mt][1] = Ps[(rm + 8) * 132 + kb + t4];
                af[mt][2] = Ps[rm * 132 + kb + t4 + 4];
                af[mt][3] = Ps[(rm + 8) * 132 + kb + t4 + 4];
            }
#pragma unroll
            for (int nt = 0; nt < 2; nt++) {
                const int cn = wn * 16 + nt * 8 + g4;
                uint32_t bf[2] = { Vs[(kb + t4) * 72 + cn], Vs[(kb + t4 + 4) * 72 + cn] };
#pragma unroll
                for (int mt = 0; mt < 2; mt++) mma_tf32(accO[mt][nt], af[mt], bf);
            }
        }
    }

    // normalize and store
    float* obase = a3v + (long)bh * LM * DH;
#pragma unroll
    for (int mt = 0; mt < 2; mt++) {
        const int r = row0 + m_woff + mt * 16 + g4;
        const float i0 = 1.0f / srow[mt][0];
        const float i1 = 1.0f / srow[mt][1];
#pragma unroll
        for (int nt = 0; nt < 2; nt++) {
            const int c = wn * 16 + nt * 8 + 2 * t4;
            *reinterpret_cast<float2*>(obase + (long)r * DH + c) =
                make_float2(accO[mt][nt][0] * i0, accO[mt][nt][1] * i0);
            *reinterpret_cast<float2*>(obase + (long)(r + 8) * DH + c) =
                make_float2(accO[mt][nt][2] * i1, accO[mt][nt][3] * i1);
        }
    }
}

// ---------------- LayerNorm (one block per token) ----------------
__global__ void ln_kernel(const float* __restrict__ x, const float* __restrict__ gamma,
                          const float* __restrict__ beta, float* __restrict__ xn)
{
    const int t = blockIdx.x;
    const int tid = threadIdx.x;
    const float2 v = reinterpret_cast<const float2*>(x + (long)t * DIM)[tid];
    float s  = v.x + v.y;
    float ss = v.x * v.x + v.y * v.y;
#pragma unroll
    for (int o = 16; o; o >>= 1) {
        s  += __shfl_xor_sync(0xffffffffu, s,  o);
        ss += __shfl_xor_sync(0xffffffffu, ss, o);
    }
    __shared__ float sms[8], smss[8];
    __shared__ float mu_s, rs_s;
    if ((tid & 31) == 0) { sms[tid >> 5] = s; smss[tid >> 5] = ss; }
    __syncthreads();
    if (tid == 0) {
        float S = 0.f, SS = 0.f;
        for (int i = 0; i < 8; i++) { S += sms[i]; SS += smss[i]; }
        const float mu = S / DIM;
        mu_s = mu;
        rs_s = rsqrtf(SS / DIM - mu * mu + 1e-5f);
    }
    __syncthreads();
    const float mu = mu_s, rs = rs_s;
    const float2 g  = reinterpret_cast<const float2*>(gamma)[tid];
    const float2 be = reinterpret_cast<const float2*>(beta)[tid];
    float2 o;
    o.x = (v.x - mu) * rs * g.x + be.x;
    o.y = (v.y - mu) * rs * g.y + be.y;
    reinterpret_cast<float2*>(xn + (long)t * DIM)[tid] = o;
}

// ---------------- landmark means (q already scaled by dh^-0.5) ----------------
__global__ void landmark_kernel(const float* __restrict__ qkv,
                                float* __restrict__ ql, float* __restrict__ kl)
{
    const int idx = blockIdx.x * blockDim.x + threadIdx.x;
    if (idx >= BH * LM * DH) return;
    const int d  = idx % DH;
    const int j  = (idx / DH) % LM;
    const int bh = idx / (DH * LM);
    const int b = bh / H, h = bh % H;
    const float* base = qkv + ((long)(b * SEQ + j * LSZ)) * QKVW + h * DH + d;
    float sq = 0.f, sk = 0.f;
#pragma unroll
    for (int l = 0; l < LSZ; l++) {
        sq += base[(long)l * QKVW];
        sk += base[(long)l * QKVW + DIM];
    }
    ql[idx] = sq * (1.0f / LSZ) * 0.125f;
    kl[idx] = sk * (1.0f / LSZ);
}

// ---------------- softmax over rows of length 256 (1 warp / row) -- for a2 ----
__global__ void softmax256(float* __restrict__ data, int rows)
{
    const int warp = (blockIdx.x * blockDim.x + threadIdx.x) >> 5;
    const int lane = threadIdx.x & 31;
    if (warp >= rows) return;
    float* r = data + (long)warp * 256;
    float v[8];
    float mx = -1e30f;
#pragma unroll
    for (int j = 0; j < 8; j++) { v[j] = r[lane + j * 32]; mx = fmaxf(mx, v[j]); }
#pragma unroll
    for (int o = 16; o; o >>= 1) mx = fmaxf(mx, __shfl_xor_sync(0xffffffffu, mx, o));
    float s = 0.f;
#pragma unroll
    for (int j = 0; j < 8; j++) { v[j] = expf(v[j] - mx); s += v[j]; }
#pragma unroll
    for (int o = 16; o; o >>= 1) s += __shfl_xor_sync(0xffffffffu, s, o);
    const float inv = 1.0f / s;
#pragma unroll
    for (int j = 0; j < 8; j++) r[lane + j * 32] = v[j] * inv;
}

// ---------------- pinv helpers ----------------
__global__ void init_norms() { g_rowmax_i = 0; g_colmax_i = 0; }

__global__ void pinv_norms(const float* __restrict__ a2)
{
    const int bh = blockIdx.x, tid = threadIdx.x;
    const float* X = a2 + (long)bh * LM * LM;
    float rs = 0.f, cs = 0.f;
    for (int j = 0; j < LM; j++) {
        rs += fabsf(X[(long)tid * LM + j]);
        cs += fabsf(X[(long)j * LM + tid]);
    }
    __shared__ float sm[256];
    sm[tid] = rs; __syncthreads();
    for (int o = 128; o; o >>= 1) { if (tid < o) sm[tid] = fmaxf(sm[tid], sm[tid + o]); __syncthreads(); }
    if (tid == 0) atomicMax(&g_rowmax_i, __float_as_int(sm[0]));
    __syncthreads();
    sm[tid] = cs; __syncthreads();
    for (int o = 128; o; o >>= 1) { if (tid < o) sm[tid] = fmaxf(sm[tid], sm[tid + o]); __syncthreads(); }
    if (tid == 0) atomicMax(&g_colmax_i, __float_as_int(sm[0]));
}

__global__ void pinv_z0(const float* __restrict__ a2, float* __restrict__ z)
{
    const long idx = (long)blockIdx.x * blockDim.x + threadIdx.x;
    if (idx >= (long)BH * LM * LM) return;
    const float inv = 1.0f / (__int_as_float(g_rowmax_i) * __int_as_float(g_colmax_i));
    const int j  = (int)(idx % LM);
    const int i  = (int)((idx / LM) % LM);
    const int bh = (int)(idx / ((long)LM * LM));
    z[idx] = a2[(long)bh * LM * LM + (long)j * LM + i] * inv;
}

// ---------------- depthwise conv over sequence (kernel 33) ----------------
__global__ void conv_kernel(const float* __restrict__ qkv, const float* __restrict__ w,
                            float* __restrict__ res)
{
    const int bh = blockIdx.y;
    const int b = bh / H, h = bh % H;
    const int i0 = blockIdx.x * 64;
    __shared__ float sm[96][DH];
    __shared__ float wsh[CK];
    const int tid = threadIdx.x;
    if (tid < CK) wsh[tid] = w[h * CK + tid];
    const float* vbase = qkv + 2 * DIM + h * DH + (long)b * SEQ * QKVW;
    for (int e = tid; e < 96 * DH; e += 256) {
        const int r = e / DH, d = e % DH;
        const int gi = i0 + r - 16;
        sm[r][d] = (gi >= 0 && gi < SEQ) ? vbase[(long)gi * QKVW + d] : 0.0f;
    }
    __syncthreads();
    float* rbase = res + (long)bh * SEQ * DH + (long)i0 * DH;
    for (int e = tid; e < 64 * DH; e += 256) {
        const int il = e / DH, d = e % DH;
        float s = 0.f;
#pragma unroll
        for (int t = 0; t < CK; t++) s = fmaf(sm[il + t][d], wsh[t], s);
        rbase[e] = s;
    }
}

// ---------------- host orchestration ----------------
extern "C" void kernel_launch(void* const* d_in, const int* in_sizes, int n_in,
                              void* d_out, int out_size)
{
    const float* x     = (const float*)d_in[0];
    const float* gamma = (const float*)d_in[1];
    const float* beta  = (const float*)d_in[2];
    const float* Wqkv  = (const float*)d_in[3];
    const float* Wout  = (const float*)d_in[4];
    const float* bout  = (const float*)d_in[5];
    const float* convw = (const float*)d_in[6];
    float* out = (float*)d_out;

    float *p_xn, *p_qkv, *p_ql, *p_kl, *p_sim1, *p_a2, *p_z, *p_z2,
          *p_xz, *p_t, *p_w, *p_a3v, *p_za3v, *p_res, *p_ctx;
    cudaGetSymbolAddress((void**)&p_xn,   g_xn);
    cudaGetSymbolAddress((void**)&p_qkv,  g_qkv);
    cudaGetSymbolAddress((void**)&p_ql,   g_ql);
    cudaGetSymbolAddress((void**)&p_kl,   g_kl);
    cudaGetSymbolAddress((void**)&p_sim1, g_sim1);
    cudaGetSymbolAddress((void**)&p_a2,   g_a2);
    cudaGetSymbolAddress((void**)&p_z,    g_z);
    cudaGetSymbolAddress((void**)&p_z2,   g_z2);
    cudaGetSymbolAddress((void**)&p_xz,   g_xz);
    cudaGetSymbolAddress((void**)&p_t,    g_t);
    cudaGetSymbolAddress((void**)&p_w,    g_w);
    cudaGetSymbolAddress((void**)&p_a3v,  g_a3v);
    cudaGetSymbolAddress((void**)&p_za3v, g_za3v);
    cudaGetSymbolAddress((void**)&p_res,  g_res);
    cudaGetSymbolAddress((void**)&p_ctx,  g_ctx);

    static bool attr_set = false;
    if (!attr_set) {
        cudaFuncSetAttribute(flash_a3v, cudaFuncAttributeMaxDynamicSharedMemorySize,
                             FL_SMEM_WORDS * 4);
        attr_set = true;
    }

    const long sQKVb = (long)SEQ * QKVW;
    const long sLD_b = (long)H * LM * DH, sLD_h = (long)LM * DH;
    const long sS1_b = (long)H * SEQ * LM, sS1_h = (long)SEQ * LM;
    const long sMM_b = (long)H * LM * LM,  sMM_h = (long)LM * LM;
    const long sOH_b = (long)H * SEQ * DH, sOH_h = (long)SEQ * DH;

    // 1) LayerNorm
    ln_kernel<<<TOK, 256>>>(x, gamma, beta, p_xn);

    // 2) QKV projection
    tgemm<128,128,16,2,4,false><<<dim3(QKVW/128, TOK/128, 1), 256>>>(
        p_xn, Wqkv, p_qkv, DIM, QKVW, QKVW, DIM,
        0,0, 0,0, 0,0, 1.0f, nullptr, nullptr, 0.f, 0, 0,0);

    // 3) landmarks
    landmark_kernel<<<(BH*LM*DH)/256, 256>>>(p_qkv, p_ql, p_kl);

    // 4) a1 = softmax(0.125 * q @ kl^T) — fused
    tgemm_sm1<<<dim3(1, SEQ/128, BH), 512>>>(p_qkv, p_kl, p_sim1);

    // 5) sim2 = q_l @ kl^T  -> a2
    tgemm<128,128,16,2,4,true><<<dim3(LM/128, LM/128, BH), 256>>>(
        p_ql, p_kl, p_a2, DH, DH, LM, DH,
        sLD_b, sLD_h, sLD_b, sLD_h, sMM_b, sMM_h, 1.0f, nullptr, nullptr, 0.f, 0, 0,0);
    softmax256<<<(BH*LM)/8, 256>>>(p_a2, BH*LM);

    // 6) a3v = softmax(q_l @ k^T) @ v — flash-fused
    flash_a3v<<<dim3(LM/64, BH), 256, FL_SMEM_WORDS * 4>>>(p_ql, p_qkv, p_a3v);

    // 7) pinv(a2) via Newton-Schulz (elementwise folded into epilogues)
    init_norms<<<1,1>>>();
    pinv_norms<<<BH, 256>>>(p_a2);
    pinv_z0<<<(BH*LM*LM)/256, 256>>>(p_a2, p_z);
    for (int it = 0; it < 6; it++) {
        float* zin  = (it & 1) ? p_z2 : p_z;
        float* zout = (it & 1) ? p_z  : p_z2;
        tgemm<128,128,16,2,4,false><<<dim3(2,2,BH), 256>>>(
            p_a2, zin, p_xz, LM, LM, LM, LM,
            sMM_b, sMM_h, sMM_b, sMM_h, sMM_b, sMM_h, 1.0f, nullptr, nullptr, 0.f, 0, 0,0);
        tgemm<128,128,16,2,4,false><<<dim3(2,2,BH), 256>>>(
            p_xz, p_xz, p_w, LM, LM, LM, LM,
            sMM_b, sMM_h, sMM_b, sMM_h, sMM_b, sMM_h, -1.0f, nullptr, p_xz, 7.0f, LM, sMM_b, sMM_h);
        tgemm<128,128,16,2,4,false><<<dim3(2,2,BH), 256>>>(
            p_xz, p_w, p_t, LM, LM, LM, LM,
            sMM_b, sMM_h, sMM_b, sMM_h, sMM_b, sMM_h, -1.0f, nullptr, p_xz, 15.0f, LM, sMM_b, sMM_h);
        tgemm<128,128,16,2,4,false><<<dim3(2,2,BH), 256>>>(
            zin, p_t, zout, LM, LM, LM, LM,
            sMM_b, sMM_h, sMM_b, sMM_h, sMM_b, sMM_h, -0.25f, nullptr, zin, 3.25f, LM, sMM_b, sMM_h);
    }

    // 8) za3v = z @ a3v
    tgemm<128,64,16,4,2,false><<<dim3(1, LM/128, BH), 256>>>(
        p_z, p_a3v, p_za3v, LM, DH, DH, LM,
        sMM_b, sMM_h, sLD_b, sLD_h, sLD_b, sLD_h, 1.0f, nullptr, nullptr, 0.f, 0, 0,0);

    // 9) depthwise conv residual over v
    conv_kernel<<<dim3(SEQ/64, BH), 256>>>(p_qkv, convw, p_res);

    // 10) ctx = a1 @ za3v + conv_res  (written directly in (b, n, h*dh) layout)
    tgemm<128,64,16,4,2,false><<<dim3(1, SEQ/128, BH), 256>>>(
        p_sim1, p_za3v, p_ctx, LM, DH, DIM, LM,
        sS1_b, sS1_h, sLD_b, sLD_h, (long)SEQ*DIM, DH,
        1.0f, nullptr, p_res, 1.0f, DH, sOH_b, sOH_h);

    // 11) final: out = ctx @ W_out + b_out + x
    tgemm<128,128,16,2,4,false><<<dim3(DIM/128, TOK/128, 1), 256>>>(
        p_ctx, Wout, out, DIM, DIM, DIM, DIM,
        0,0, 0,0, 0,0, 1.0f, bout, x, 1.0f, DIM, 0,0);
}